// round 4
// baseline (speedup 1.0000x reference)
#include <cuda_runtime.h>
#include <math.h>
#include <stdint.h>
#include <stddef.h>

#define T_   128
#define B_   64
#define D_   256
#define H_   512
#define R_   4
#define N_   128
#define W_   64
#define HR   768
#define NIF  471
#define NIFP 480

// ---------------- persistent state ----------------
__device__ float g_h[2][B_*H_];
__device__ float g_hT[H_*B_];
__device__ float g_s[B_*H_];
__device__ float g_r[B_*R_*W_];
__device__ float g_rw[B_*N_*R_];
__device__ float g_ww[B_*N_];
__device__ float g_u[B_*N_];
__device__ float g_p[B_*N_];
__device__ float g_mem[B_*N_*W_];
__device__ float g_links[B_*N_*N_];
__device__ float g_if[B_*NIFP];

__device__ __forceinline__ float sigm(float x) { return 1.f/(1.f+expf(-x)); }
__device__ __forceinline__ float oneplus(float v) {
    float sp = (v > 20.f) ? v : log1pf(expf(v));
    return 1.f + sp;
}

// ---------------- init ----------------
__global__ void k_init(const float* __restrict__ M0) {
    int i = blockIdx.x*blockDim.x + threadIdx.x;
    int stride = gridDim.x*blockDim.x;
    for (int idx = i; idx < B_*N_*N_; idx += stride) g_links[idx] = 0.f;
    for (int idx = i; idx < B_*N_*W_; idx += stride) g_mem[idx] = M0[idx % (N_*W_)];
    for (int idx = i; idx < B_*H_;    idx += stride) { g_h[0][idx]=0.f; g_h[1][idx]=0.f; g_s[idx]=0.f; }
    for (int idx = i; idx < B_*R_*W_; idx += stride) g_r[idx]=0.f;
    for (int idx = i; idx < B_*N_*R_; idx += stride) g_rw[idx]=0.f;
    for (int idx = i; idx < B_*N_;    idx += stride) { g_ww[idx]=0.f; g_u[idx]=1e-6f; g_p[idx]=0.f; }
}

// ---------------- K1: gates GEMM + LSTM pointwise ----------------
// grid 128 blocks (4 h-cols each), 256 threads: thread = (jl 0..3, b 0..63)
__global__ void __launch_bounds__(256) k_gates(
    const float* __restrict__ x, const float* __restrict__ W_ih, const float* __restrict__ b_ih,
    const float* __restrict__ W_hh, const float* __restrict__ b_hh,
    float* __restrict__ out, int t)
{
    __shared__ float aS[64*68];
    __shared__ float wS[16*64];

    int tid = threadIdx.x;
    int jl  = tid >> 6;
    int b   = tid & 63;
    int jbase = blockIdx.x * 4;
    int j = jbase + jl;
    const float* hprev = g_h[t & 1];

    float acc0=0.f, acc1=0.f, acc2=0.f, acc3=0.f;

    for (int chunk = 0; chunk < 16; chunk++) {
        int k0 = chunk * 64;
        for (int idx = tid; idx < 4096; idx += 256) {
            int bb = idx >> 6, kk = idx & 63;
            int k = k0 + kk;
            float v;
            if (k < 256)      v = x[((size_t)t*B_ + bb)*D_ + k];
            else if (k < 512) v = g_r[bb*256 + (k-256)];
            else              v = hprev[bb*H_ + (k-512)];
            aS[bb*68 + kk] = v;
        }
        for (int idx = tid; idx < 1024; idx += 256) {
            int row = idx >> 6, kk = idx & 63;
            int c = row >> 2, g = row & 3;
            int G = g*H_ + jbase + c;
            float v = (k0 < 512) ? W_ih[(size_t)G*512 + k0 + kk]
                                 : W_hh[(size_t)G*512 + (k0-512) + kk];
            wS[row*64 + kk] = v;
        }
        __syncthreads();

        const float4* a4 = reinterpret_cast<const float4*>(aS + b*68);
        const float4* w0 = reinterpret_cast<const float4*>(wS + (jl*4+0)*64);
        const float4* w1 = reinterpret_cast<const float4*>(wS + (jl*4+1)*64);
        const float4* w2 = reinterpret_cast<const float4*>(wS + (jl*4+2)*64);
        const float4* w3 = reinterpret_cast<const float4*>(wS + (jl*4+3)*64);
        #pragma unroll
        for (int q = 0; q < 16; q++) {
            float4 av = a4[q];
            float4 v0 = w0[q], v1 = w1[q], v2 = w2[q], v3 = w3[q];
            acc0 = fmaf(av.x,v0.x,fmaf(av.y,v0.y,fmaf(av.z,v0.z,fmaf(av.w,v0.w,acc0))));
            acc1 = fmaf(av.x,v1.x,fmaf(av.y,v1.y,fmaf(av.z,v1.z,fmaf(av.w,v1.w,acc1))));
            acc2 = fmaf(av.x,v2.x,fmaf(av.y,v2.y,fmaf(av.z,v2.z,fmaf(av.w,v2.w,acc2))));
            acc3 = fmaf(av.x,v3.x,fmaf(av.y,v3.y,fmaf(av.z,v3.z,fmaf(av.w,v3.w,acc3))));
        }
        __syncthreads();
    }

    float gi = acc0 + b_ih[0*H_+j] + b_hh[0*H_+j];
    float gf = acc1 + b_ih[1*H_+j] + b_hh[1*H_+j];
    float gg = acc2 + b_ih[2*H_+j] + b_hh[2*H_+j];
    float go = acc3 + b_ih[3*H_+j] + b_hh[3*H_+j];

    float sold = g_s[b*H_+j];
    float snew = sigm(gf)*sold + sigm(gi)*tanhf(gg);
    float hnew = sigm(go)*tanhf(snew);
    g_s[b*H_+j] = snew;
    g_h[(t&1)^1][b*H_+j] = hnew;
    g_hT[j*B_ + b] = hnew;
    out[((size_t)t*B_ + b)*HR + j] = hnew;
}

// ---------------- K2: interface projections (pre-activation) ----------------
__global__ void __launch_bounds__(256) k_iface(
    const float* __restrict__ Wrk, const float* __restrict__ brk,
    const float* __restrict__ Wrs, const float* __restrict__ brs,
    const float* __restrict__ Wwk, const float* __restrict__ bwk,
    const float* __restrict__ Wws, const float* __restrict__ bws,
    const float* __restrict__ We,  const float* __restrict__ be,
    const float* __restrict__ Wv,  const float* __restrict__ bv,
    const float* __restrict__ Wfg, const float* __restrict__ bfg,
    const float* __restrict__ Wag, const float* __restrict__ bag,
    const float* __restrict__ Wwg, const float* __restrict__ bwg,
    const float* __restrict__ Wrm, const float* __restrict__ brm)
{
    __shared__ float wSm[4*512];
    __shared__ float biasS[4];
    int tid = threadIdx.x;
    int c = tid >> 6, b = tid & 63;
    int Cbase = blockIdx.x * 4;

    for (int idx = tid; idx < 2048; idx += 256) {
        int cc = idx >> 9, k = idx & 511;
        int C = Cbase + cc;
        const float* wp = nullptr;
        if (C < 256)       { int w = C>>2, r = C&3; wp = Wrk + ((size_t)r*W_ + w)*H_; }
        else if (C < 260)  wp = Wrs + (C-256)*H_;
        else if (C < 272)  wp = Wrm + (C-260)*H_;
        else if (C < 276)  wp = Wfg + (C-272)*H_;
        else if (C < 340)  wp = Wwk + (C-276)*H_;
        else if (C == 340) wp = Wws;
        else if (C < 405)  wp = We + (C-341)*H_;
        else if (C < 469)  wp = Wv + (C-405)*H_;
        else if (C == 469) wp = Wag;
        else if (C == 470) wp = Wwg;
        wSm[cc*512 + k] = wp ? wp[k] : 0.f;
    }
    if (tid < 4) {
        int C = Cbase + tid; float bb = 0.f;
        if (C < 256)       { int w = C>>2, r = C&3; bb = brk[r*W_ + w]; }
        else if (C < 260)  bb = brs[C-256];
        else if (C < 272)  bb = brm[C-260];
        else if (C < 276)  bb = bfg[C-272];
        else if (C < 340)  bb = bwk[C-276];
        else if (C == 340) bb = bws[0];
        else if (C < 405)  bb = be[C-341];
        else if (C < 469)  bb = bv[C-405];
        else if (C == 469) bb = bag[0];
        else if (C == 470) bb = bwg[0];
        biasS[tid] = bb;
    }
    __syncthreads();

    int C = Cbase + c;
    if (C < NIF) {
        float acc = 0.f;
        const float* wp = wSm + c*512;
        #pragma unroll 8
        for (int k = 0; k < 512; k++) acc = fmaf(g_hT[k*B_ + b], wp[k], acc);
        g_if[b*NIFP + C] = acc + biasS[c];
    }
}

// ---------------- K3: full DNC state update, one block per batch ----------------
#define SM_STATE_FLOATS (8192+16512+512*5+128*6+256+64*3+4+4+12+4+8+16)
#define SM_STATE_BYTES  (SM_STATE_FLOATS*4)

__global__ void __launch_bounds__(256) k_state(float* __restrict__ out, int t)
{
    extern __shared__ float sm[];
    float* memS   = sm;
    float* linkS  = memS + 8192;          // [128][129]
    float* rwoldT = linkS + 16512;        // [r][n]
    float* rwnew  = rwoldT + 512;         // [n][r]
    float* crS    = rwnew + 512;          // [n][r]
    float* fwdS   = crS + 512;
    float* bwdS   = fwdS + 512;
    float* wwS    = bwdS + 512;
    float* pS     = wwS + 128;
    float* aS     = pS + 128;
    float* suS    = aS + 128;
    float* cwS    = suS + 128;
    float* normM  = cwS + 128;
    float* rkS    = normM + 128;          // [r][w]
    float* wkS    = rkS + 256;
    float* erS    = wkS + 64;
    float* wvS    = erS + 64;
    float* fgS    = wvS + 64;
    float* rsS    = fgS + 4;
    float* rmS    = rsS + 4;              // [r][m]
    float* rknS   = rmS + 12;
    float* scal   = rknS + 4;             // 0:wkn 1:ws 2:ag 3:wg 4:S 5:cwmax 6:cwsum
    float* red    = scal + 8;             // [r]: max,sum

    int b   = blockIdx.x;
    int tid = threadIdx.x;
    int lane = tid & 31, wid = tid >> 5;
    const float* ifr = g_if + b*NIFP;

    // ---- stage ----
    for (int idx = tid; idx < N_*W_; idx += 256) memS[idx] = g_mem[(size_t)b*N_*W_ + idx];
    for (int idx = tid; idx < N_*N_; idx += 256) {
        int i = idx >> 7, j = idx & 127;
        linkS[i*129 + j] = g_links[(size_t)b*N_*N_ + idx];
    }
    for (int idx = tid; idx < N_*R_; idx += 256)
        rwoldT[(idx & 3)*128 + (idx >> 2)] = g_rw[b*N_*R_ + idx];
    { int w = tid >> 2, r = tid & 3; rkS[r*64 + w] = ifr[tid]; }
    if (tid < 64) {
        wkS[tid] = ifr[276 + tid];
        erS[tid] = sigm(ifr[341 + tid]);
        wvS[tid] = sigm(ifr[405 + tid]);
    }
    if (tid < 4) {
        fgS[tid] = sigm(ifr[272 + tid]);
        rsS[tid] = oneplus(ifr[256 + tid]);
        float m0 = ifr[260 + tid*3 + 0], m1 = ifr[260 + tid*3 + 1], m2 = ifr[260 + tid*3 + 2];
        float mx = fmaxf(m0, fmaxf(m1, m2));
        float e0 = expf(m0-mx), e1 = expf(m1-mx), e2 = expf(m2-mx);
        float si = e0 + e1 + e2;
        rmS[tid*3+0] = e0/si; rmS[tid*3+1] = e1/si; rmS[tid*3+2] = e2/si;
    }
    if (tid == 0) {
        scal[1] = oneplus(ifr[340]);
        scal[2] = sigm(ifr[469]);
        scal[3] = sigm(ifr[470]);
    }
    __syncthreads();

    // ---- old mem norms, key norms, usage ----
    for (int n = wid; n < N_; n += 8) {
        float v0 = memS[n*64+lane], v1 = memS[n*64+lane+32];
        float ss = v0*v0 + v1*v1;
        for (int o = 16; o; o >>= 1) ss += __shfl_xor_sync(0xffffffffu, ss, o);
        if (lane == 0) normM[n] = sqrtf(ss);
    }
    if (wid == 0) {
        float v = wkS[lane]*wkS[lane] + wkS[lane+32]*wkS[lane+32];
        for (int o = 16; o; o >>= 1) v += __shfl_xor_sync(0xffffffffu, v, o);
        if (lane == 0) scal[0] = sqrtf(v);
    }
    if (wid >= 1 && wid <= 4) {
        int r = wid - 1;
        float a0 = rkS[r*64+lane], a1 = rkS[r*64+lane+32];
        float ss = a0*a0 + a1*a1;
        for (int o = 16; o; o >>= 1) ss += __shfl_xor_sync(0xffffffffu, ss, o);
        if (lane == 0) rknS[r] = sqrtf(ss);
    }
    if (tid < 128) {
        float psi = (1.f - fgS[0]*rwoldT[0*128+tid]) * (1.f - fgS[1]*rwoldT[1*128+tid])
                  * (1.f - fgS[2]*rwoldT[2*128+tid]) * (1.f - fgS[3]*rwoldT[3*128+tid]);
        float uo = g_u[b*N_+tid], wo = g_ww[b*N_+tid];
        float un = (uo + wo - uo*wo) * psi;
        suS[tid] = un;
        g_u[b*N_+tid] = un;
    }
    __syncthreads();

    // ---- bitonic sort ascending ----
    for (int k = 2; k <= 128; k <<= 1) {
        for (int j = k >> 1; j > 0; j >>= 1) {
            if (tid < 128) {
                int ixj = tid ^ j;
                if (ixj > tid) {
                    float va = suS[tid], vb = suS[ixj];
                    bool up = ((tid & k) == 0);
                    if ((va > vb) == up) { suS[tid] = vb; suS[ixj] = va; }
                }
            }
            __syncthreads();
        }
    }

    // ---- inclusive prefix product, then allocation (kept sorted: faithful) ----
    if (tid < 128) aS[tid] = suS[tid];
    __syncthreads();
    for (int off = 1; off < 128; off <<= 1) {
        float v = (tid < 128 && tid >= off) ? aS[tid-off] : 1.f;
        __syncthreads();
        if (tid < 128 && tid >= off) aS[tid] *= v;
        __syncthreads();
    }
    float excl = (tid > 0 && tid < 128) ? aS[tid-1] : 1.f;
    __syncthreads();
    if (tid < 128) aS[tid] = (1.f - suS[tid]) * excl;
    __syncthreads();

    // ---- content write scores (old mem) ----
    {
        float wkn = scal[0], ws = scal[1];
        for (int n = wid; n < N_; n += 8) {
            float d = memS[n*64+lane]*wkS[lane] + memS[n*64+lane+32]*wkS[lane+32];
            for (int o = 16; o; o >>= 1) d += __shfl_xor_sync(0xffffffffu, d, o);
            if (lane == 0) cwS[n] = d / ((normM[n] + 1e-6f) * wkn) * ws;
        }
    }
    __syncthreads();
    if (wid == 0) {
        float m = fmaxf(fmaxf(cwS[lane], cwS[lane+32]), fmaxf(cwS[lane+64], cwS[lane+96]));
        for (int o = 16; o; o >>= 1) m = fmaxf(m, __shfl_xor_sync(0xffffffffu, m, o));
        float s_ = expf(cwS[lane]-m) + expf(cwS[lane+32]-m) + expf(cwS[lane+64]-m) + expf(cwS[lane+96]-m);
        for (int o = 16; o; o >>= 1) s_ += __shfl_xor_sync(0xffffffffu, s_, o);
        if (lane == 0) { scal[5] = m; scal[6] = s_; }
    }
    __syncthreads();
    if (tid < 128) cwS[tid] = expf(cwS[tid] - scal[5]) / scal[6];
    __syncthreads();

    // ---- ww, sum, precedence ----
    if (tid < 128) {
        float w = scal[3] * (scal[2]*aS[tid] + (1.f - scal[2])*cwS[tid]);
        wwS[tid] = w;
        g_ww[b*N_+tid] = w;
    }
    __syncthreads();
    if (wid == 0) {
        float s_ = wwS[lane] + wwS[lane+32] + wwS[lane+64] + wwS[lane+96];
        for (int o = 16; o; o >>= 1) s_ += __shfl_xor_sync(0xffffffffu, s_, o);
        if (lane == 0) scal[4] = s_;
    }
    __syncthreads();
    if (tid < 128) {
        float pn = (1.f - scal[4]) * g_p[b*N_+tid] + wwS[tid];
        pS[tid] = pn;
        g_p[b*N_+tid] = pn;
    }
    __syncthreads();

    // ---- memory write + new norms ----
    for (int n = wid; n < N_; n += 8) {
        float w0 = memS[n*64+lane]    + wwS[n]*(wvS[lane]    - erS[lane]);
        float w1 = memS[n*64+lane+32] + wwS[n]*(wvS[lane+32] - erS[lane+32]);
        memS[n*64+lane]    = w0;
        memS[n*64+lane+32] = w1;
        g_mem[(size_t)b*N_*W_ + n*64 + lane]      = w0;
        g_mem[(size_t)b*N_*W_ + n*64 + lane + 32] = w1;
        float ss = w0*w0 + w1*w1;
        for (int o = 16; o; o >>= 1) ss += __shfl_xor_sync(0xffffffffu, ss, o);
        if (lane == 0) normM[n] = sqrtf(ss);
    }
    __syncthreads();

    // ---- temporal links (new precedence) ----
    for (int idx = tid; idx < N_*N_; idx += 256) {
        int i = idx >> 7, j = idx & 127;
        float L = linkS[i*129 + j];
        L = (1.f - wwS[i] - wwS[j]) * L + wwS[i]*pS[j];
        if (i == j) L = 0.f;
        linkS[i*129 + j] = L;
        g_links[(size_t)b*N_*N_ + idx] = L;
    }
    __syncthreads();

    // ---- fwd/bwd walks (old rw, new links) + content-read scores (new mem) ----
    for (int n = wid; n < N_; n += 8) {
        float f0=0,f1=0,f2=0,f3=0, g0=0,g1=0,g2=0,g3=0;
        #pragma unroll
        for (int q = 0; q < 4; q++) {
            int j = lane + q*32;
            float Lnj = linkS[n*129 + j];
            float Ljn = linkS[j*129 + n];
            float r0 = rwoldT[0*128+j], r1 = rwoldT[1*128+j], r2 = rwoldT[2*128+j], r3 = rwoldT[3*128+j];
            f0 += Lnj*r0; f1 += Lnj*r1; f2 += Lnj*r2; f3 += Lnj*r3;
            g0 += Ljn*r0; g1 += Ljn*r1; g2 += Ljn*r2; g3 += Ljn*r3;
        }
        float m0 = memS[n*64+lane], m1 = memS[n*64+lane+32];
        float c0 = m0*rkS[0*64+lane] + m1*rkS[0*64+lane+32];
        float c1 = m0*rkS[1*64+lane] + m1*rkS[1*64+lane+32];
        float c2 = m0*rkS[2*64+lane] + m1*rkS[2*64+lane+32];
        float c3 = m0*rkS[3*64+lane] + m1*rkS[3*64+lane+32];
        for (int o = 16; o; o >>= 1) {
            f0 += __shfl_xor_sync(0xffffffffu, f0, o);
            f1 += __shfl_xor_sync(0xffffffffu, f1, o);
            f2 += __shfl_xor_sync(0xffffffffu, f2, o);
            f3 += __shfl_xor_sync(0xffffffffu, f3, o);
            g0 += __shfl_xor_sync(0xffffffffu, g0, o);
            g1 += __shfl_xor_sync(0xffffffffu, g1, o);
            g2 += __shfl_xor_sync(0xffffffffu, g2, o);
            g3 += __shfl_xor_sync(0xffffffffu, g3, o);
            c0 += __shfl_xor_sync(0xffffffffu, c0, o);
            c1 += __shfl_xor_sync(0xffffffffu, c1, o);
            c2 += __shfl_xor_sync(0xffffffffu, c2, o);
            c3 += __shfl_xor_sync(0xffffffffu, c3, o);
        }
        if (lane == 0) {
            fwdS[n*4+0]=f0; fwdS[n*4+1]=f1; fwdS[n*4+2]=f2; fwdS[n*4+3]=f3;
            bwdS[n*4+0]=g0; bwdS[n*4+1]=g1; bwdS[n*4+2]=g2; bwdS[n*4+3]=g3;
            float inv = 1.f/(normM[n] + 1e-6f);
            crS[n*4+0] = c0*inv/rknS[0]*rsS[0];
            crS[n*4+1] = c1*inv/rknS[1]*rsS[1];
            crS[n*4+2] = c2*inv/rknS[2]*rsS[2];
            crS[n*4+3] = c3*inv/rknS[3]*rsS[3];
        }
    }
    __syncthreads();

    // ---- cr softmax per head ----
    if (wid < 4) {
        int r = wid;
        float m = -1e30f;
        #pragma unroll
        for (int q = 0; q < 4; q++) m = fmaxf(m, crS[(lane + q*32)*4 + r]);
        for (int o = 16; o; o >>= 1) m = fmaxf(m, __shfl_xor_sync(0xffffffffu, m, o));
        float s_ = 0.f;
        #pragma unroll
        for (int q = 0; q < 4; q++) s_ += expf(crS[(lane + q*32)*4 + r] - m);
        for (int o = 16; o; o >>= 1) s_ += __shfl_xor_sync(0xffffffffu, s_, o);
        if (lane == 0) { red[r*2] = m; red[r*2+1] = s_; }
    }
    __syncthreads();

    // ---- new read weights ----
    if (tid < 128) {
        int n = tid;
        #pragma unroll
        for (int r = 0; r < 4; r++) {
            float c = expf(crS[n*4+r] - red[r*2]) / red[r*2+1];
            float v = rmS[r*3+0]*bwdS[n*4+r] + rmS[r*3+1]*c + rmS[r*3+2]*fwdS[n*4+r];
            rwnew[n*4+r] = v;
            g_rw[b*N_*R_ + n*4 + r] = v;
        }
    }
    __syncthreads();

    // ---- read vectors: rv[w,r] = sum_n mem[n,w]*rw[n,r] ----
    {
        int w = tid >> 2, r = tid & 3;
        float acc = 0.f;
        #pragma unroll 4
        for (int n = 0; n < 128; n++) acc = fmaf(memS[n*64+w], rwnew[n*4+r], acc);
        g_r[b*256 + w*4 + r] = acc;
        out[((size_t)t*B_ + b)*HR + 512 + w*4 + r] = acc;
    }
}

// ---------------- tail: copy hrs[-1] ----------------
__global__ void k_tail(float* __restrict__ out) {
    int i = blockIdx.x*blockDim.x + threadIdx.x;
    if (i < B_*HR) out[(size_t)T_*B_*HR + i] = out[(size_t)(T_-1)*B_*HR + i];
}

extern "C" void kernel_launch(void* const* d_in, const int* in_sizes, int n_in,
                              void* d_out, int out_size) {
    const float* x    = (const float*)d_in[0];
    const float* M0   = (const float*)d_in[1];
    const float* W_ih = (const float*)d_in[2];
    const float* b_ih = (const float*)d_in[3];
    const float* W_hh = (const float*)d_in[4];
    const float* b_hh = (const float*)d_in[5];
    const float* Wrk  = (const float*)d_in[6];
    const float* brk  = (const float*)d_in[7];
    const float* Wrs  = (const float*)d_in[8];
    const float* brs  = (const float*)d_in[9];
    const float* Wwk  = (const float*)d_in[10];
    const float* bwk  = (const float*)d_in[11];
    const float* Wws  = (const float*)d_in[12];
    const float* bws  = (const float*)d_in[13];
    const float* We   = (const float*)d_in[14];
    const float* be   = (const float*)d_in[15];
    const float* Wv   = (const float*)d_in[16];
    const float* bv   = (const float*)d_in[17];
    const float* Wfg  = (const float*)d_in[18];
    const float* bfg  = (const float*)d_in[19];
    const float* Wag  = (const float*)d_in[20];
    const float* bag  = (const float*)d_in[21];
    const float* Wwg  = (const float*)d_in[22];
    const float* bwg  = (const float*)d_in[23];
    const float* Wrm  = (const float*)d_in[24];
    const float* brm  = (const float*)d_in[25];
    float* out = (float*)d_out;

    cudaFuncSetAttribute(k_state, cudaFuncAttributeMaxDynamicSharedMemorySize, SM_STATE_BYTES);

    k_init<<<256, 256>>>(M0);
    for (int t = 0; t < T_; t++) {
        k_gates<<<128, 256>>>(x, W_ih, b_ih, W_hh, b_hh, out, t);
        k_iface<<<118, 256>>>(Wrk,brk,Wrs,brs,Wwk,bwk,Wws,bws,We,be,Wv,bv,
                              Wfg,bfg,Wag,bag,Wwg,bwg,Wrm,brm);
        k_state<<<64, 256, SM_STATE_BYTES>>>(out, t);
    }
    k_tail<<<48, 1024>>>(out);
}

// round 5
// speedup vs baseline: 2.0573x; 2.0573x over previous
#include <cuda_runtime.h>
#include <math.h>
#include <stdint.h>
#include <stddef.h>

#define T_   128
#define B_   64
#define D_   256
#define H_   512
#define R_   4
#define N_   128
#define W_   64
#define HR   768
#define NIF  471
#define NIFP 480

// ---------------- persistent state (16B aligned for float4 access) ----------------
__device__ __align__(16) float g_h[2][B_*H_];
__device__ __align__(16) float g_hT[H_*B_];
__device__ __align__(16) float g_s[B_*H_];
__device__ __align__(16) float g_r[B_*R_*W_];
__device__ __align__(16) float g_rw[B_*N_*R_];
__device__ __align__(16) float g_ww[B_*N_];
__device__ __align__(16) float g_u[B_*N_];
__device__ __align__(16) float g_p[B_*N_];
__device__ __align__(16) float g_mem[B_*N_*W_];
__device__ __align__(16) float g_links[B_*N_*N_];
__device__ __align__(16) float g_if[B_*NIFP];

__device__ __forceinline__ float sigm(float x) { return 1.f/(1.f+expf(-x)); }
__device__ __forceinline__ float oneplus(float v) {
    float sp = (v > 20.f) ? v : log1pf(expf(v));
    return 1.f + sp;
}

// ---------------- init ----------------
__global__ void k_init(const float* __restrict__ M0) {
    int i = blockIdx.x*blockDim.x + threadIdx.x;
    int stride = gridDim.x*blockDim.x;
    for (int idx = i; idx < B_*N_*N_; idx += stride) g_links[idx] = 0.f;
    for (int idx = i; idx < B_*N_*W_; idx += stride) g_mem[idx] = M0[idx % (N_*W_)];
    for (int idx = i; idx < B_*H_;    idx += stride) { g_h[0][idx]=0.f; g_h[1][idx]=0.f; g_s[idx]=0.f; }
    for (int idx = i; idx < B_*R_*W_; idx += stride) g_r[idx]=0.f;
    for (int idx = i; idx < B_*N_*R_; idx += stride) g_rw[idx]=0.f;
    for (int idx = i; idx < B_*N_;    idx += stride) { g_ww[idx]=0.f; g_u[idx]=1e-6f; g_p[idx]=0.f; }
}

// ---------------- K1: gates GEMM + LSTM pointwise ----------------
__global__ void __launch_bounds__(256) k_gates(
    const float* __restrict__ x, const float* __restrict__ W_ih, const float* __restrict__ b_ih,
    const float* __restrict__ W_hh, const float* __restrict__ b_hh,
    float* __restrict__ out, int t)
{
    __shared__ float aS[64*68];
    __shared__ float wS[16*64];

    int tid = threadIdx.x;
    int jl  = tid >> 6;
    int b   = tid & 63;
    int jbase = blockIdx.x * 4;
    int j = jbase + jl;
    const float* hprev = g_h[t & 1];

    float acc0=0.f, acc1=0.f, acc2=0.f, acc3=0.f;

    for (int chunk = 0; chunk < 16; chunk++) {
        int k0 = chunk * 64;
        // chunk-uniform source (chunks 0-3: x, 4-7: g_r, 8-15: hprev)
        const float* src; int stride;
        if (k0 < 256)      { src = x + (size_t)t*B_*D_ + k0; stride = D_; }
        else if (k0 < 512) { src = g_r + (k0-256);           stride = 256; }
        else               { src = hprev + (k0-512);         stride = H_; }
        #pragma unroll
        for (int q = 0; q < 4; q++) {
            int f = tid + 256*q;          // 0..1023 float4s
            int bb = f >> 4, k4 = f & 15;
            float4 v = *(const float4*)(src + (size_t)bb*stride + k4*4);
            *(float4*)(aS + bb*68 + k4*4) = v;
        }
        {
            int row = tid >> 4, k4 = tid & 15;
            int c = row >> 2, g = row & 3;
            int G = g*H_ + jbase + c;
            const float* wp = (k0 < 512) ? (W_ih + (size_t)G*512 + k0)
                                         : (W_hh + (size_t)G*512 + (k0-512));
            *(float4*)(wS + row*64 + k4*4) = *(const float4*)(wp + k4*4);
        }
        __syncthreads();

        const float4* a4 = reinterpret_cast<const float4*>(aS + b*68);
        const float4* w0 = reinterpret_cast<const float4*>(wS + (jl*4+0)*64);
        const float4* w1 = reinterpret_cast<const float4*>(wS + (jl*4+1)*64);
        const float4* w2 = reinterpret_cast<const float4*>(wS + (jl*4+2)*64);
        const float4* w3 = reinterpret_cast<const float4*>(wS + (jl*4+3)*64);
        #pragma unroll
        for (int q = 0; q < 16; q++) {
            float4 av = a4[q];
            float4 v0 = w0[q], v1 = w1[q], v2 = w2[q], v3 = w3[q];
            acc0 = fmaf(av.x,v0.x,fmaf(av.y,v0.y,fmaf(av.z,v0.z,fmaf(av.w,v0.w,acc0))));
            acc1 = fmaf(av.x,v1.x,fmaf(av.y,v1.y,fmaf(av.z,v1.z,fmaf(av.w,v1.w,acc1))));
            acc2 = fmaf(av.x,v2.x,fmaf(av.y,v2.y,fmaf(av.z,v2.z,fmaf(av.w,v2.w,acc2))));
            acc3 = fmaf(av.x,v3.x,fmaf(av.y,v3.y,fmaf(av.z,v3.z,fmaf(av.w,v3.w,acc3))));
        }
        __syncthreads();
    }

    float gi = acc0 + b_ih[0*H_+j] + b_hh[0*H_+j];
    float gf = acc1 + b_ih[1*H_+j] + b_hh[1*H_+j];
    float gg = acc2 + b_ih[2*H_+j] + b_hh[2*H_+j];
    float go = acc3 + b_ih[3*H_+j] + b_hh[3*H_+j];

    float sold = g_s[b*H_+j];
    float snew = sigm(gf)*sold + sigm(gi)*tanhf(gg);
    float hnew = sigm(go)*tanhf(snew);
    g_s[b*H_+j] = snew;
    g_h[(t&1)^1][b*H_+j] = hnew;
    g_hT[j*B_ + b] = hnew;
    out[((size_t)t*B_ + b)*HR + j] = hnew;
}

// ---------------- K2: interface projections (pre-activation) ----------------
__global__ void __launch_bounds__(256) k_iface(
    const float* __restrict__ Wrk, const float* __restrict__ brk,
    const float* __restrict__ Wrs, const float* __restrict__ brs,
    const float* __restrict__ Wwk, const float* __restrict__ bwk,
    const float* __restrict__ Wws, const float* __restrict__ bws,
    const float* __restrict__ We,  const float* __restrict__ be,
    const float* __restrict__ Wv,  const float* __restrict__ bv,
    const float* __restrict__ Wfg, const float* __restrict__ bfg,
    const float* __restrict__ Wag, const float* __restrict__ bag,
    const float* __restrict__ Wwg, const float* __restrict__ bwg,
    const float* __restrict__ Wrm, const float* __restrict__ brm)
{
    __shared__ float wSm[4*512];
    __shared__ float biasS[4];
    int tid = threadIdx.x;
    int c = tid >> 6, b = tid & 63;
    int Cbase = blockIdx.x * 4;

    for (int idx = tid; idx < 2048; idx += 256) {
        int cc = idx >> 9, k = idx & 511;
        int C = Cbase + cc;
        const float* wp = nullptr;
        if (C < 256)       { int w = C>>2, r = C&3; wp = Wrk + ((size_t)r*W_ + w)*H_; }
        else if (C < 260)  wp = Wrs + (C-256)*H_;
        else if (C < 272)  wp = Wrm + (C-260)*H_;
        else if (C < 276)  wp = Wfg + (C-272)*H_;
        else if (C < 340)  wp = Wwk + (C-276)*H_;
        else if (C == 340) wp = Wws;
        else if (C < 405)  wp = We + (C-341)*H_;
        else if (C < 469)  wp = Wv + (C-405)*H_;
        else if (C == 469) wp = Wag;
        else if (C == 470) wp = Wwg;
        wSm[cc*512 + k] = wp ? wp[k] : 0.f;
    }
    if (tid < 4) {
        int C = Cbase + tid; float bb = 0.f;
        if (C < 256)       { int w = C>>2, r = C&3; bb = brk[r*W_ + w]; }
        else if (C < 260)  bb = brs[C-256];
        else if (C < 272)  bb = brm[C-260];
        else if (C < 276)  bb = bfg[C-272];
        else if (C < 340)  bb = bwk[C-276];
        else if (C == 340) bb = bws[0];
        else if (C < 405)  bb = be[C-341];
        else if (C < 469)  bb = bv[C-405];
        else if (C == 469) bb = bag[0];
        else if (C == 470) bb = bwg[0];
        biasS[tid] = bb;
    }
    __syncthreads();

    int C = Cbase + c;
    if (C < NIF) {
        float acc = 0.f;
        const float* wp = wSm + c*512;
        #pragma unroll 8
        for (int k = 0; k < 512; k++) acc = fmaf(g_hT[k*B_ + b], wp[k], acc);
        g_if[b*NIFP + C] = acc + biasS[c];
    }
}

// ---------------- K3: full DNC state update, one block per batch ----------------
// smem (floats): mem 8192 | links 128*129 | rwoldT 512 | rwnew 512 | cr 512 | fwd 512
//   | bwd 512 | bwdP 4096 | ww 128 | p 128 | pOld 128 | a 128 | su 128 | cw 128
//   | normM 128 | rk 256 | wk 64 | er 64 | wv 64 | fg 4 | rs 4 | rm 12 | rkn 4 | scal 8 | red 8
#define SM_STATE_FLOATS (8192+16512+512*5+4096+128*7+256+64*3+4+4+12+4+8+8)
#define SM_STATE_BYTES  (SM_STATE_FLOATS*4)

__global__ void __launch_bounds__(256) k_state(float* __restrict__ out, int t)
{
    extern __shared__ float sm[];
    float* memS   = sm;
    float* linkS  = memS + 8192;          // [128][129]
    float* rwoldT = linkS + 16512;        // [r][n]
    float* rwnew  = rwoldT + 512;         // [n][r]
    float* crS    = rwnew + 512;          // [n][r]
    float* fwdS   = crS + 512;            // [n][r]
    float* bwdS   = fwdS + 512;           // [n][r]
    float* bwdP   = bwdS + 512;           // [8][j*4+r] partials
    float* wwS    = bwdP + 4096;
    float* pS     = wwS + 128;
    float* pOld   = pS + 128;
    float* aS     = pOld + 128;
    float* suS    = aS + 128;
    float* cwS    = suS + 128;
    float* normM  = cwS + 128;
    float* rkS    = normM + 128;          // [r][w]
    float* wkS    = rkS + 256;
    float* erS    = wkS + 64;
    float* wvS    = erS + 64;
    float* fgS    = wvS + 64;
    float* rsS    = fgS + 4;
    float* rmS    = rsS + 4;              // [r][m]
    float* rknS   = rmS + 12;
    float* scal   = rknS + 4;             // 0:wkn 1:ws 2:ag 3:wg
    float* red    = scal + 8;             // [r]: max,sum

    int b   = blockIdx.x;
    int tid = threadIdx.x;
    int lane = tid & 31, wid = tid >> 5;
    const float* ifr = g_if + b*NIFP;
    const unsigned FULL = 0xffffffffu;

    // ---- stage (float4) ----
    {
        const float4* gm4 = (const float4*)(g_mem + (size_t)b*N_*W_);
        float4* mem4 = (float4*)memS;
        #pragma unroll
        for (int q = 0; q < 8; q++) mem4[tid + 256*q] = gm4[tid + 256*q];
        const float4* gl4 = (const float4*)(g_links + (size_t)b*N_*N_);
        #pragma unroll
        for (int q = 0; q < 16; q++) {
            int i = tid + 256*q;          // 4096 float4s
            float4 v = gl4[i];
            int row = i >> 5, col = (i & 31) << 2;
            float* d = linkS + row*129 + col;
            d[0]=v.x; d[1]=v.y; d[2]=v.z; d[3]=v.w;
        }
    }
    #pragma unroll
    for (int q = 0; q < 2; q++) {
        int i = tid + 256*q;
        rwoldT[(i & 3)*128 + (i >> 2)] = g_rw[b*N_*R_ + i];
    }
    { int w = tid >> 2, r = tid & 3; rkS[r*64 + w] = ifr[tid]; }
    if (tid < 128) pOld[tid] = g_p[b*N_ + tid];
    if (tid < 64) {
        wkS[tid] = ifr[276 + tid];
        erS[tid] = sigm(ifr[341 + tid]);
        wvS[tid] = sigm(ifr[405 + tid]);
    }
    if (tid < 4) {
        fgS[tid] = sigm(ifr[272 + tid]);
        rsS[tid] = oneplus(ifr[256 + tid]);
        float m0 = ifr[260 + tid*3 + 0], m1 = ifr[260 + tid*3 + 1], m2 = ifr[260 + tid*3 + 2];
        float mx = fmaxf(m0, fmaxf(m1, m2));
        float e0 = expf(m0-mx), e1 = expf(m1-mx), e2 = expf(m2-mx);
        float si = e0 + e1 + e2;
        rmS[tid*3+0] = e0/si; rmS[tid*3+1] = e1/si; rmS[tid*3+2] = e2/si;
    }
    if (tid == 0) {
        scal[1] = oneplus(ifr[340]);
        scal[2] = sigm(ifr[469]);
        scal[3] = sigm(ifr[470]);
    }
    __syncthreads();  // B1

    // ---- phase 1: old mem norms, key norms, usage ----
    for (int n = wid; n < N_; n += 8) {
        float v0 = memS[n*64+lane], v1 = memS[n*64+lane+32];
        float ss = v0*v0 + v1*v1;
        #pragma unroll
        for (int o = 16; o; o >>= 1) ss += __shfl_xor_sync(FULL, ss, o);
        if (lane == 0) normM[n] = sqrtf(ss);
    }
    if (wid == 0) {
        float v = wkS[lane]*wkS[lane] + wkS[lane+32]*wkS[lane+32];
        #pragma unroll
        for (int o = 16; o; o >>= 1) v += __shfl_xor_sync(FULL, v, o);
        if (lane == 0) scal[0] = sqrtf(v);
    }
    if (wid >= 1 && wid <= 4) {
        int r = wid - 1;
        float a0 = rkS[r*64+lane], a1 = rkS[r*64+lane+32];
        float ss = a0*a0 + a1*a1;
        #pragma unroll
        for (int o = 16; o; o >>= 1) ss += __shfl_xor_sync(FULL, ss, o);
        if (lane == 0) rknS[r] = sqrtf(ss);
    }
    if (tid < 128) {
        float psi = (1.f - fgS[0]*rwoldT[0*128+tid]) * (1.f - fgS[1]*rwoldT[1*128+tid])
                  * (1.f - fgS[2]*rwoldT[2*128+tid]) * (1.f - fgS[3]*rwoldT[3*128+tid]);
        float uo = g_u[b*N_+tid], wo = g_ww[b*N_+tid];
        float un = (uo + wo - uo*wo) * psi;
        suS[tid] = un;
        g_u[b*N_+tid] = un;
    }
    __syncthreads();  // B2

    // ---- phase 2: warp0 = sort+scan+alloc; warps1-7 = content write scores ----
    if (wid == 0) {
        // bitonic sort ascending, element e = s*32 + lane, 4 regs/lane
        float v[4];
        #pragma unroll
        for (int s = 0; s < 4; s++) v[s] = suS[s*32 + lane];
        #pragma unroll
        for (int k = 2; k <= 128; k <<= 1) {
            for (int j = k >> 1; j >= 32; j >>= 1) {       // register stages
                int js = j >> 5;
                #pragma unroll
                for (int s = 0; s < 4; s++) if (!(s & js)) {
                    int sp = s | js;
                    bool up = (((s*32 + lane) & k) == 0);
                    float lo = v[s], hi = v[sp];
                    float mn = fminf(lo, hi), mx = fmaxf(lo, hi);
                    v[s]  = up ? mn : mx;
                    v[sp] = up ? mx : mn;
                }
            }
            for (int j = ((k>>1) > 16 ? 16 : (k>>1)); j >= 1; j >>= 1) {  // shfl stages
                #pragma unroll
                for (int s = 0; s < 4; s++) {
                    bool up = (((s*32 + lane) & k) == 0);
                    float o = __shfl_xor_sync(FULL, v[s], j);
                    bool lower = ((lane & j) == 0);
                    v[s] = (up == lower) ? fminf(v[s], o) : fmaxf(v[s], o);
                }
            }
        }
        // transpose to rank = lane*4+q via smem (warp-private)
        #pragma unroll
        for (int s = 0; s < 4; s++) suS[s*32 + lane] = v[s];
        __syncwarp();
        float w0 = suS[lane*4+0], w1 = suS[lane*4+1], w2 = suS[lane*4+2], w3 = suS[lane*4+3];
        float pl = w0*w1*w2*w3;
        float incl = pl;
        #pragma unroll
        for (int off = 1; off < 32; off <<= 1) {
            float tv = __shfl_up_sync(FULL, incl, off);
            if (lane >= off) incl *= tv;
        }
        float base = __shfl_up_sync(FULL, incl, 1);
        if (lane == 0) base = 1.f;
        float run = base;
        aS[lane*4+0] = (1.f - w0)*run; run *= w0;
        aS[lane*4+1] = (1.f - w1)*run; run *= w1;
        aS[lane*4+2] = (1.f - w2)*run; run *= w2;
        aS[lane*4+3] = (1.f - w3)*run;
    } else {
        float wkn = scal[0], ws = scal[1];
        float k0 = wkS[lane], k1 = wkS[lane+32];
        for (int n = wid - 1; n < N_; n += 7) {
            float d = memS[n*64+lane]*k0 + memS[n*64+lane+32]*k1;
            #pragma unroll
            for (int o = 16; o; o >>= 1) d += __shfl_xor_sync(FULL, d, o);
            if (lane == 0) cwS[n] = d / ((normM[n] + 1e-6f) * wkn) * ws;
        }
    }
    __syncthreads();  // B3

    // ---- phase 3: warp0 serial chunk: cw softmax -> ww -> S -> p ----
    if (wid == 0) {
        float c0 = cwS[lane*4+0], c1 = cwS[lane*4+1], c2 = cwS[lane*4+2], c3 = cwS[lane*4+3];
        float mx = fmaxf(fmaxf(c0,c1), fmaxf(c2,c3));
        #pragma unroll
        for (int o = 16; o; o >>= 1) mx = fmaxf(mx, __shfl_xor_sync(FULL, mx, o));
        float e0 = expf(c0-mx), e1 = expf(c1-mx), e2 = expf(c2-mx), e3 = expf(c3-mx);
        float sme = e0+e1+e2+e3;
        #pragma unroll
        for (int o = 16; o; o >>= 1) sme += __shfl_xor_sync(FULL, sme, o);
        float inv = 1.f/sme;
        float ag = scal[2], wg = scal[3];
        float ww0 = wg*(ag*aS[lane*4+0] + (1.f-ag)*e0*inv);
        float ww1 = wg*(ag*aS[lane*4+1] + (1.f-ag)*e1*inv);
        float ww2 = wg*(ag*aS[lane*4+2] + (1.f-ag)*e2*inv);
        float ww3 = wg*(ag*aS[lane*4+3] + (1.f-ag)*e3*inv);
        wwS[lane*4+0]=ww0; wwS[lane*4+1]=ww1; wwS[lane*4+2]=ww2; wwS[lane*4+3]=ww3;
        g_ww[b*N_+lane*4+0]=ww0; g_ww[b*N_+lane*4+1]=ww1;
        g_ww[b*N_+lane*4+2]=ww2; g_ww[b*N_+lane*4+3]=ww3;
        float S = ww0+ww1+ww2+ww3;
        #pragma unroll
        for (int o = 16; o; o >>= 1) S += __shfl_xor_sync(FULL, S, o);
        float oms = 1.f - S;
        float p0 = oms*pOld[lane*4+0] + ww0;
        float p1 = oms*pOld[lane*4+1] + ww1;
        float p2 = oms*pOld[lane*4+2] + ww2;
        float p3 = oms*pOld[lane*4+3] + ww3;
        pS[lane*4+0]=p0; pS[lane*4+1]=p1; pS[lane*4+2]=p2; pS[lane*4+3]=p3;
        g_p[b*N_+lane*4+0]=p0; g_p[b*N_+lane*4+1]=p1;
        g_p[b*N_+lane*4+2]=p2; g_p[b*N_+lane*4+3]=p3;
    }
    __syncthreads();  // B4

    // ---- phase 4: mem write + new-norm + content-read scores (fused) ----
    {
        float er0 = erS[lane], er1 = erS[lane+32];
        float wv0 = wvS[lane], wv1 = wvS[lane+32];
        float rka[4], rkb[4], rsr[4], rknr[4];
        #pragma unroll
        for (int r = 0; r < 4; r++) {
            rka[r] = rkS[r*64+lane]; rkb[r] = rkS[r*64+lane+32];
            rsr[r] = rsS[r]; rknr[r] = rknS[r];
        }
        for (int n = wid; n < N_; n += 8) {
            float wwn = wwS[n];
            float m0 = memS[n*64+lane]    + wwn*(wv0 - er0);
            float m1 = memS[n*64+lane+32] + wwn*(wv1 - er1);
            memS[n*64+lane]    = m0;
            memS[n*64+lane+32] = m1;
            g_mem[(size_t)b*N_*W_ + n*64 + lane]      = m0;
            g_mem[(size_t)b*N_*W_ + n*64 + lane + 32] = m1;
            float ss = m0*m0 + m1*m1;
            float c[4];
            #pragma unroll
            for (int r = 0; r < 4; r++) c[r] = m0*rka[r] + m1*rkb[r];
            #pragma unroll
            for (int o = 16; o; o >>= 1) {
                ss += __shfl_xor_sync(FULL, ss, o);
                c[0] += __shfl_xor_sync(FULL, c[0], o);
                c[1] += __shfl_xor_sync(FULL, c[1], o);
                c[2] += __shfl_xor_sync(FULL, c[2], o);
                c[3] += __shfl_xor_sync(FULL, c[3], o);
            }
            if (lane == 0) {
                float invn = 1.f/(sqrtf(ss) + 1e-6f);
                #pragma unroll
                for (int r = 0; r < 4; r++) crS[n*4+r] = c[r]*invn/rknr[r]*rsr[r];
            }
        }
    }
    __syncthreads();  // B5

    // ---- phase 5: links update + fwd walk + bwd partials (fused) ----
    {
        float rj[4][4], pj[4], wwj[4], bw[4][4];
        #pragma unroll
        for (int q = 0; q < 4; q++) {
            pj[q] = pS[lane+32*q]; wwj[q] = wwS[lane+32*q];
            #pragma unroll
            for (int r = 0; r < 4; r++) { rj[r][q] = rwoldT[r*128 + lane + 32*q]; bw[q][r] = 0.f; }
        }
        int i0 = wid*16;
        for (int ii = 0; ii < 16; ii++) {
            int i = i0 + ii;
            float wi = wwS[i];
            float ri[4];
            #pragma unroll
            for (int r = 0; r < 4; r++) ri[r] = rwoldT[r*128 + i];
            float f[4] = {0.f, 0.f, 0.f, 0.f};
            #pragma unroll
            for (int q = 0; q < 4; q++) {
                int j = lane + 32*q;
                float L = linkS[i*129 + j];
                L = (1.f - wi - wwj[q])*L + wi*pj[q];
                if (i == j) L = 0.f;
                linkS[i*129 + j] = L;
                g_links[(size_t)b*N_*N_ + i*128 + j] = L;
                #pragma unroll
                for (int r = 0; r < 4; r++) {
                    f[r]     = fmaf(L, rj[r][q], f[r]);
                    bw[q][r] = fmaf(L, ri[r],    bw[q][r]);
                }
            }
            #pragma unroll
            for (int o = 16; o; o >>= 1) {
                f[0] += __shfl_xor_sync(FULL, f[0], o);
                f[1] += __shfl_xor_sync(FULL, f[1], o);
                f[2] += __shfl_xor_sync(FULL, f[2], o);
                f[3] += __shfl_xor_sync(FULL, f[3], o);
            }
            if (lane == 0) {
                #pragma unroll
                for (int r = 0; r < 4; r++) fwdS[i*4+r] = f[r];
            }
        }
        #pragma unroll
        for (int q = 0; q < 4; q++)
            #pragma unroll
            for (int r = 0; r < 4; r++)
                bwdP[wid*512 + (lane+32*q)*4 + r] = bw[q][r];
    }
    __syncthreads();  // B6

    // ---- phase 6: cr softmax (warps 0-3) + bwd reduce (warps 4-7) ----
    if (wid < 4) {
        int r = wid;
        float m = -1e30f;
        #pragma unroll
        for (int q = 0; q < 4; q++) m = fmaxf(m, crS[(lane + 32*q)*4 + r]);
        #pragma unroll
        for (int o = 16; o; o >>= 1) m = fmaxf(m, __shfl_xor_sync(FULL, m, o));
        float s_ = 0.f;
        #pragma unroll
        for (int q = 0; q < 4; q++) s_ += expf(crS[(lane + 32*q)*4 + r] - m);
        #pragma unroll
        for (int o = 16; o; o >>= 1) s_ += __shfl_xor_sync(FULL, s_, o);
        if (lane == 0) { red[r*2] = m; red[r*2+1] = s_; }
    } else {
        int t2 = (wid - 4)*32 + lane;     // 0..127
        #pragma unroll
        for (int q = 0; q < 4; q++) {
            int jr = t2 + 128*q;          // 0..511, conflict-free
            float acc = 0.f;
            #pragma unroll
            for (int w8 = 0; w8 < 8; w8++) acc += bwdP[w8*512 + jr];
            bwdS[jr] = acc;
        }
    }
    __syncthreads();  // B7

    // ---- phase 7: new read weights ----
    if (tid < 128) {
        int n = tid;
        #pragma unroll
        for (int r = 0; r < 4; r++) {
            float c = expf(crS[n*4+r] - red[r*2]) / red[r*2+1];
            float v = rmS[r*3+0]*bwdS[n*4+r] + rmS[r*3+1]*c + rmS[r*3+2]*fwdS[n*4+r];
            rwnew[n*4+r] = v;
            g_rw[b*N_*R_ + n*4 + r] = v;
        }
    }
    __syncthreads();  // B8

    // ---- phase 8: read vectors ----
    {
        int w = tid >> 2, r = tid & 3;
        float acc = 0.f;
        #pragma unroll 8
        for (int n = 0; n < 128; n++) acc = fmaf(memS[n*64+w], rwnew[n*4+r], acc);
        g_r[b*256 + w*4 + r] = acc;
        out[((size_t)t*B_ + b)*HR + 512 + w*4 + r] = acc;
    }
}

// ---------------- tail: copy hrs[-1] ----------------
__global__ void k_tail(float* __restrict__ out) {
    int i = blockIdx.x*blockDim.x + threadIdx.x;
    if (i < B_*HR) out[(size_t)T_*B_*HR + i] = out[(size_t)(T_-1)*B_*HR + i];
}

extern "C" void kernel_launch(void* const* d_in, const int* in_sizes, int n_in,
                              void* d_out, int out_size) {
    const float* x    = (const float*)d_in[0];
    const float* M0   = (const float*)d_in[1];
    const float* W_ih = (const float*)d_in[2];
    const float* b_ih = (const float*)d_in[3];
    const float* W_hh = (const float*)d_in[4];
    const float* b_hh = (const float*)d_in[5];
    const float* Wrk  = (const float*)d_in[6];
    const float* brk  = (const float*)d_in[7];
    const float* Wrs  = (const float*)d_in[8];
    const float* brs  = (const float*)d_in[9];
    const float* Wwk  = (const float*)d_in[10];
    const float* bwk  = (const float*)d_in[11];
    const float* Wws  = (const float*)d_in[12];
    const float* bws  = (const float*)d_in[13];
    const float* We   = (const float*)d_in[14];
    const float* be   = (const float*)d_in[15];
    const float* Wv   = (const float*)d_in[16];
    const float* bv   = (const float*)d_in[17];
    const float* Wfg  = (const float*)d_in[18];
    const float* bfg  = (const float*)d_in[19];
    const float* Wag  = (const float*)d_in[20];
    const float* bag  = (const float*)d_in[21];
    const float* Wwg  = (const float*)d_in[22];
    const float* bwg  = (const float*)d_in[23];
    const float* Wrm  = (const float*)d_in[24];
    const float* brm  = (const float*)d_in[25];
    float* out = (float*)d_out;

    cudaFuncSetAttribute(k_state, cudaFuncAttributeMaxDynamicSharedMemorySize, SM_STATE_BYTES);

    k_init<<<256, 256>>>(M0);
    for (int t = 0; t < T_; t++) {
        k_gates<<<128, 256>>>(x, W_ih, b_ih, W_hh, b_hh, out, t);
        k_iface<<<118, 256>>>(Wrk,brk,Wrs,brs,Wwk,bwk,Wws,bws,We,be,Wv,bv,
                              Wfg,bfg,Wag,bag,Wwg,bwg,Wrm,brm);
        k_state<<<64, 256, SM_STATE_BYTES>>>(out, t);
    }
    k_tail<<<48, 1024>>>(out);
}

// round 7
// speedup vs baseline: 2.4502x; 1.1910x over previous
#include <cuda_runtime.h>
#include <math.h>
#include <stdint.h>
#include <stddef.h>

#define T_   128
#define B_   64
#define D_   256
#define H_   512
#define R_   4
#define N_   128
#define W_   64
#define HR   768
#define NIF  471
#define NIFP 480
#define GRID_ 128
#define TPB_  512

// ---------------- cross-block global state ----------------
__device__ __align__(16) float g_h[2][B_*H_];
__device__ __align__(16) float g_hT[H_*B_];
__device__ __align__(16) float g_r[B_*R_*W_];
__device__ __align__(16) float g_if[B_*NIFP];
__device__ unsigned g_bar;

__device__ __forceinline__ float sigm(float x) { return 1.f/(1.f+expf(-x)); }
__device__ __forceinline__ float oneplus(float v) {
    float sp = (v > 20.f) ? v : log1pf(expf(v));
    return 1.f + sp;
}

// software grid barrier: all GRID_ blocks co-resident (1 CTA/SM via smem)
__device__ __forceinline__ void gbar(unsigned &tgt) {
    __syncthreads();
    if (threadIdx.x == 0) {
        __threadfence();
        atomicAdd(&g_bar, 1u);
        unsigned v;
        do {
            asm volatile("ld.acquire.gpu.u32 %0, [%1];" : "=r"(v) : "l"(&g_bar) : "memory");
            if (v < tgt) __nanosleep(20);
        } while (v < tgt);
    }
    __syncthreads();
    tgt += GRID_;
}

// ---------------- init ----------------
__global__ void k_init() {
    int i = blockIdx.x*blockDim.x + threadIdx.x;
    int stride = gridDim.x*blockDim.x;
    for (int idx = i; idx < 2*B_*H_; idx += stride) ((float*)g_h)[idx] = 0.f;
    for (int idx = i; idx < H_*B_;   idx += stride) g_hT[idx] = 0.f;
    for (int idx = i; idx < B_*R_*W_; idx += stride) g_r[idx] = 0.f;
    if (i == 0) g_bar = 0u;
}

// smem layout (floats)
#define OFF_LINK 0                         // [128][129] = 16512
#define OFF_MEM  16512                     // 8192
#define OFF_RWT  (16512+8192)              // rwoldT [r][n] 512
#define OFF_U    (OFF_RWT+512)             // 128
#define OFF_P    (OFF_U+128)               // 128
#define OFF_WW   (OFF_P+128)               // 128
#define OFF_S    (OFF_WW+128)              // sS 256 (LSTM cell state, 4 cols x 64 b)
#define OFF_SCR  (OFF_S+256)               // scratch union base (11240 floats)
#define SM_FLOATS (OFF_SCR + 11240)
#define SM_BYTES  (SM_FLOATS*4)

__global__ void __launch_bounds__(TPB_, 1) k_dnc(
    const float* __restrict__ x, const float* __restrict__ M0,
    const float* __restrict__ W_ih, const float* __restrict__ b_ih,
    const float* __restrict__ W_hh, const float* __restrict__ b_hh,
    const float* __restrict__ Wrk, const float* __restrict__ brk,
    const float* __restrict__ Wrs, const float* __restrict__ brs,
    const float* __restrict__ Wwk, const float* __restrict__ bwk,
    const float* __restrict__ Wws, const float* __restrict__ bws,
    const float* __restrict__ We,  const float* __restrict__ be,
    const float* __restrict__ Wv,  const float* __restrict__ bv,
    const float* __restrict__ Wfg, const float* __restrict__ bfg,
    const float* __restrict__ Wag, const float* __restrict__ bag,
    const float* __restrict__ Wwg, const float* __restrict__ bwg,
    const float* __restrict__ Wrm, const float* __restrict__ brm,
    float* __restrict__ out)
{
    extern __shared__ float sm[];
    float* linkS  = sm + OFF_LINK;
    float* memS   = sm + OFF_MEM;
    float* rwoldT = sm + OFF_RWT;
    float* uS     = sm + OFF_U;
    float* pPer   = sm + OFF_P;
    float* wwPer  = sm + OFF_WW;
    float* sS     = sm + OFF_S;
    float* scr    = sm + OFF_SCR;
    // gates scratch
    float* aS = scr;             // 4352 = 64*68
    float* wS = scr + 4352;      // 1024 = 16*64
    float* gS = scr + 5376;      // 1024 = 16*64
    // iface scratch (aliases gates)
    float* hTs   = scr;          // 4352
    float* wSm   = scr + 4352;   // 512 = 8*64
    float* biasS = scr + 4864;   // 8
    // state scratch (aliases)
    float* rwnewS= scr;          // 512 [n][r]
    float* crS   = scr + 512;    // 512
    float* fwdS  = scr + 1024;   // 512
    float* bwdS  = scr + 1536;   // 512
    float* bwdP  = scr + 2048;   // 8192 = 16 warps x 512
    float* suS   = scr + 10240;  // 128
    float* aAl   = scr + 10368;  // 128
    float* cwS   = scr + 10496;  // 128
    float* normM = scr + 10624;  // 128
    float* rkS   = scr + 10752;  // 256 [r][w]
    float* wkS   = scr + 11008;  // 64
    float* erS   = scr + 11072;  // 64
    float* wvS   = scr + 11136;  // 64
    float* fgS   = scr + 11200;  // 4
    float* rsS   = scr + 11204;  // 4
    float* rmS   = scr + 11208;  // 12
    float* rknS  = scr + 11220;  // 4
    float* scal  = scr + 11224;  // 8 (0:wkn 1:ws 2:ag 3:wg)
    float* red   = scr + 11232;  // 8

    const int tid  = threadIdx.x;
    const int lane = tid & 31, wid = tid >> 5;
    const int bid  = blockIdx.x;
    const unsigned FULL = 0xffffffffu;
    unsigned tgt = GRID_;

    // ---- one-time smem init ----
    if (bid < 64) {
        for (int i = tid; i < N_*W_; i += TPB_) memS[i] = M0[i];
        for (int i = tid; i < 16512; i += TPB_) linkS[i] = 0.f;
        if (tid < 512) rwoldT[tid] = 0.f;
        if (tid < 128) { uS[tid] = 1e-6f; pPer[tid] = 0.f; wwPer[tid] = 0.f; }
    }
    if (tid < 256) sS[tid] = 0.f;
    __syncthreads();

    const int jbase = bid * 4;
    const int row8  = tid >> 6;      // 0..7
    const int bb_   = tid & 63;

    for (int t = 0; t < T_; t++) {
        // ================= gates phase (all 128 blocks) =================
        {
            const float* hprev = g_h[t & 1];
            float acc0 = 0.f, acc1 = 0.f;
            for (int chunk = 0; chunk < 16; chunk++) {
                int k0 = chunk * 64;
                #pragma unroll
                for (int q = 0; q < 2; q++) {
                    int f = tid + TPB_*q;            // 0..1023 float4s
                    int bb = f >> 4, k4 = f & 15;
                    float4 v;
                    if (k0 < 256)
                        v = *(const float4*)(x + ((size_t)t*B_ + bb)*D_ + k0 + k4*4);
                    else if (k0 < 512)
                        v = __ldcg((const float4*)(g_r + bb*256 + (k0-256) + k4*4));
                    else
                        v = __ldcg((const float4*)(hprev + bb*H_ + (k0-512) + k4*4));
                    *(float4*)(aS + bb*68 + k4*4) = v;
                }
                if (tid < 256) {
                    int row = tid >> 4, k4 = tid & 15;
                    int c = row >> 2, g = row & 3;
                    int G = g*H_ + jbase + c;
                    const float* wp = (k0 < 512) ? (W_ih + (size_t)G*512 + k0)
                                                 : (W_hh + (size_t)G*512 + (k0-512));
                    *(float4*)(wS + row*64 + k4*4) = *(const float4*)(wp + k4*4);
                }
                __syncthreads();
                const float4* a4 = (const float4*)(aS + bb_*68);
                const float4* w0 = (const float4*)(wS + row8*64);
                const float4* w1 = (const float4*)(wS + (row8+8)*64);
                #pragma unroll
                for (int q = 0; q < 16; q++) {
                    float4 av = a4[q], v0 = w0[q], v1 = w1[q];
                    acc0 = fmaf(av.x,v0.x,fmaf(av.y,v0.y,fmaf(av.z,v0.z,fmaf(av.w,v0.w,acc0))));
                    acc1 = fmaf(av.x,v1.x,fmaf(av.y,v1.y,fmaf(av.z,v1.z,fmaf(av.w,v1.w,acc1))));
                }
                __syncthreads();
            }
            gS[row8*64 + bb_]     = acc0;
            gS[(row8+8)*64 + bb_] = acc1;
            __syncthreads();
            if (tid < 256) {
                int jl = tid >> 6, b2 = tid & 63;
                int j = jbase + jl;
                float gi = gS[(jl*4+0)*64+b2] + b_ih[0*H_+j] + b_hh[0*H_+j];
                float gf = gS[(jl*4+1)*64+b2] + b_ih[1*H_+j] + b_hh[1*H_+j];
                float gg = gS[(jl*4+2)*64+b2] + b_ih[2*H_+j] + b_hh[2*H_+j];
                float go = gS[(jl*4+3)*64+b2] + b_ih[3*H_+j] + b_hh[3*H_+j];
                float sold = sS[jl*64+b2];
                float snew = sigm(gf)*sold + sigm(gi)*tanhf(gg);
                float hnew = sigm(go)*tanhf(snew);
                sS[jl*64+b2] = snew;
                g_h[(t&1)^1][b2*H_ + j] = hnew;
                g_hT[j*B_ + b2] = hnew;
                out[((size_t)t*B_ + b2)*HR + j] = hnew;
            }
        }
        gbar(tgt);   // hT visible

        // ================= iface phase (blocks 0..58, 8 cols each) =================
        if (bid < 59) {
            int Cbase = bid * 8;
            int c = tid >> 6, b2 = tid & 63;
            if (tid < 8) {
                int C = Cbase + tid; float bb = 0.f;
                if (C < 256)       { int w = C>>2, r = C&3; bb = brk[r*W_ + w]; }
                else if (C < 260)  bb = brs[C-256];
                else if (C < 272)  bb = brm[C-260];
                else if (C < 276)  bb = bfg[C-272];
                else if (C < 340)  bb = bwk[C-276];
                else if (C == 340) bb = bws[0];
                else if (C < 405)  bb = be[C-341];
                else if (C < 469)  bb = bv[C-405];
                else if (C == 469) bb = bag[0];
                else if (C == 470) bb = bwg[0];
                biasS[tid] = bb;
            }
            float acc = 0.f;
            for (int chunk = 0; chunk < 8; chunk++) {
                int k0 = chunk * 64;
                #pragma unroll
                for (int q = 0; q < 2; q++) {
                    int f = tid + TPB_*q;
                    int kk = f >> 4, c4 = f & 15;
                    float4 v = __ldcg((const float4*)(g_hT + (k0+kk)*B_ + c4*4));
                    *(float4*)(hTs + kk*68 + c4*4) = v;
                }
                {
                    int cc = tid >> 6, kk = tid & 63;
                    int C = Cbase + cc;
                    const float* wp = nullptr;
                    if (C < 256)       { int w = C>>2, r = C&3; wp = Wrk + ((size_t)r*W_ + w)*H_; }
                    else if (C < 260)  wp = Wrs + (C-256)*H_;
                    else if (C < 272)  wp = Wrm + (C-260)*H_;
                    else if (C < 276)  wp = Wfg + (C-272)*H_;
                    else if (C < 340)  wp = Wwk + (C-276)*H_;
                    else if (C == 340) wp = Wws;
                    else if (C < 405)  wp = We + (C-341)*H_;
                    else if (C < 469)  wp = Wv + (C-405)*H_;
                    else if (C == 469) wp = Wag;
                    else if (C == 470) wp = Wwg;
                    wSm[cc*64 + kk] = wp ? wp[k0 + kk] : 0.f;
                }
                __syncthreads();
                #pragma unroll
                for (int kk = 0; kk < 64; kk++)
                    acc = fmaf(hTs[kk*68 + b2], wSm[c*64 + kk], acc);
                __syncthreads();
            }
            int C = Cbase + c;
            if (C < NIF) g_if[b2*NIFP + C] = acc + biasS[c];
        }
        gbar(tgt);   // g_if visible

        // ================= state phase (blocks 0..63) =================
        if (bid < 64) {
            const int b = bid;
            const float* ifr = g_if + b*NIFP;

            // S0: interface unpack
            if (tid < 256) { int w = tid >> 2, r = tid & 3; rkS[r*64 + w] = __ldcg(ifr + tid); }
            else if (tid < 320) { int i = tid-256; wkS[i] = __ldcg(ifr + 276 + i); }
            else if (tid < 384) { int i = tid-320; erS[i] = sigm(__ldcg(ifr + 341 + i)); }
            else if (tid < 448) { int i = tid-384; wvS[i] = sigm(__ldcg(ifr + 405 + i)); }
            else if (tid < 452) {
                int i = tid-448;
                fgS[i] = sigm(__ldcg(ifr + 272 + i));
                rsS[i] = oneplus(__ldcg(ifr + 256 + i));
                float m0 = __ldcg(ifr+260+i*3+0), m1 = __ldcg(ifr+260+i*3+1), m2 = __ldcg(ifr+260+i*3+2);
                float mx = fmaxf(m0, fmaxf(m1, m2));
                float e0 = expf(m0-mx), e1 = expf(m1-mx), e2 = expf(m2-mx);
                float si = e0+e1+e2;
                rmS[i*3+0]=e0/si; rmS[i*3+1]=e1/si; rmS[i*3+2]=e2/si;
            }
            else if (tid == 500) {
                scal[1] = oneplus(__ldcg(ifr + 340));
                scal[2] = sigm(__ldcg(ifr + 469));
                scal[3] = sigm(__ldcg(ifr + 470));
            }
            __syncthreads();

            // P1: old mem norms, key norms, usage
            for (int n = wid; n < N_; n += 16) {
                float v0 = memS[n*64+lane], v1 = memS[n*64+lane+32];
                float ss = v0*v0 + v1*v1;
                #pragma unroll
                for (int o = 16; o; o >>= 1) ss += __shfl_xor_sync(FULL, ss, o);
                if (lane == 0) normM[n] = sqrtf(ss);
            }
            if (wid == 0) {
                float v = wkS[lane]*wkS[lane] + wkS[lane+32]*wkS[lane+32];
                #pragma unroll
                for (int o = 16; o; o >>= 1) v += __shfl_xor_sync(FULL, v, o);
                if (lane == 0) scal[0] = sqrtf(v);
            }
            if (wid >= 1 && wid <= 4) {
                int r = wid - 1;
                float a0 = rkS[r*64+lane], a1 = rkS[r*64+lane+32];
                float ss = a0*a0 + a1*a1;
                #pragma unroll
                for (int o = 16; o; o >>= 1) ss += __shfl_xor_sync(FULL, ss, o);
                if (lane == 0) rknS[r] = sqrtf(ss);
            }
            if (tid < 128) {
                float psi = (1.f - fgS[0]*rwoldT[0*128+tid]) * (1.f - fgS[1]*rwoldT[1*128+tid])
                          * (1.f - fgS[2]*rwoldT[2*128+tid]) * (1.f - fgS[3]*rwoldT[3*128+tid]);
                float uo = uS[tid], wo = wwPer[tid];
                float un = (uo + wo - uo*wo) * psi;
                suS[tid] = un;
                uS[tid] = un;
            }
            __syncthreads();

            // P2: warp0 sort+scan+alloc; warps 1-15 content write scores
            if (wid == 0) {
                float v[4];
                #pragma unroll
                for (int s = 0; s < 4; s++) v[s] = suS[s*32 + lane];
                #pragma unroll
                for (int k = 2; k <= 128; k <<= 1) {
                    for (int j = k >> 1; j >= 32; j >>= 1) {
                        int js = j >> 5;
                        #pragma unroll
                        for (int s = 0; s < 4; s++) if (!(s & js)) {
                            int sp = s | js;
                            bool up = (((s*32 + lane) & k) == 0);
                            float lo = v[s], hi = v[sp];
                            float mn = fminf(lo, hi), mx = fmaxf(lo, hi);
                            v[s]  = up ? mn : mx;
                            v[sp] = up ? mx : mn;
                        }
                    }
                    for (int j = ((k>>1) > 16 ? 16 : (k>>1)); j >= 1; j >>= 1) {
                        #pragma unroll
                        for (int s = 0; s < 4; s++) {
                            bool up = (((s*32 + lane) & k) == 0);
                            float o = __shfl_xor_sync(FULL, v[s], j);
                            bool lower = ((lane & j) == 0);
                            v[s] = (up == lower) ? fminf(v[s], o) : fmaxf(v[s], o);
                        }
                    }
                }
                #pragma unroll
                for (int s = 0; s < 4; s++) suS[s*32 + lane] = v[s];
                __syncwarp();
                float w0 = suS[lane*4+0], w1 = suS[lane*4+1], w2 = suS[lane*4+2], w3 = suS[lane*4+3];
                float pl = w0*w1*w2*w3;
                float incl = pl;
                #pragma unroll
                for (int off = 1; off < 32; off <<= 1) {
                    float tv = __shfl_up_sync(FULL, incl, off);
                    if (lane >= off) incl *= tv;
                }
                float base = __shfl_up_sync(FULL, incl, 1);
                if (lane == 0) base = 1.f;
                float run = base;
                aAl[lane*4+0] = (1.f - w0)*run; run *= w0;
                aAl[lane*4+1] = (1.f - w1)*run; run *= w1;
                aAl[lane*4+2] = (1.f - w2)*run; run *= w2;
                aAl[lane*4+3] = (1.f - w3)*run;
            } else {
                float wkn = scal[0], ws = scal[1];
                float k0 = wkS[lane], k1 = wkS[lane+32];
                for (int n = wid - 1; n < N_; n += 15) {
                    float d = memS[n*64+lane]*k0 + memS[n*64+lane+32]*k1;
                    #pragma unroll
                    for (int o = 16; o; o >>= 1) d += __shfl_xor_sync(FULL, d, o);
                    if (lane == 0) cwS[n] = d / ((normM[n] + 1e-6f) * wkn) * ws;
                }
            }
            __syncthreads();

            // P3: warp0: cw softmax -> ww -> sum -> precedence
            if (wid == 0) {
                float c0 = cwS[lane*4+0], c1 = cwS[lane*4+1], c2 = cwS[lane*4+2], c3 = cwS[lane*4+3];
                float mx = fmaxf(fmaxf(c0,c1), fmaxf(c2,c3));
                #pragma unroll
                for (int o = 16; o; o >>= 1) mx = fmaxf(mx, __shfl_xor_sync(FULL, mx, o));
                float e0 = expf(c0-mx), e1 = expf(c1-mx), e2 = expf(c2-mx), e3 = expf(c3-mx);
                float sme = e0+e1+e2+e3;
                #pragma unroll
                for (int o = 16; o; o >>= 1) sme += __shfl_xor_sync(FULL, sme, o);
                float inv = 1.f/sme;
                float ag = scal[2], wg = scal[3];
                float ww0 = wg*(ag*aAl[lane*4+0] + (1.f-ag)*e0*inv);
                float ww1 = wg*(ag*aAl[lane*4+1] + (1.f-ag)*e1*inv);
                float ww2 = wg*(ag*aAl[lane*4+2] + (1.f-ag)*e2*inv);
                float ww3 = wg*(ag*aAl[lane*4+3] + (1.f-ag)*e3*inv);
                wwPer[lane*4+0]=ww0; wwPer[lane*4+1]=ww1; wwPer[lane*4+2]=ww2; wwPer[lane*4+3]=ww3;
                float S = ww0+ww1+ww2+ww3;
                #pragma unroll
                for (int o = 16; o; o >>= 1) S += __shfl_xor_sync(FULL, S, o);
                float oms = 1.f - S;
                pPer[lane*4+0] = oms*pPer[lane*4+0] + ww0;
                pPer[lane*4+1] = oms*pPer[lane*4+1] + ww1;
                pPer[lane*4+2] = oms*pPer[lane*4+2] + ww2;
                pPer[lane*4+3] = oms*pPer[lane*4+3] + ww3;
            }
            __syncthreads();

            // P4: mem write + new norm + content-read scores (fused)
            {
                float er0 = erS[lane], er1 = erS[lane+32];
                float wv0 = wvS[lane], wv1 = wvS[lane+32];
                float rka[4], rkb[4], rsr[4], rknr[4];
                #pragma unroll
                for (int r = 0; r < 4; r++) {
                    rka[r] = rkS[r*64+lane]; rkb[r] = rkS[r*64+lane+32];
                    rsr[r] = rsS[r]; rknr[r] = rknS[r];
                }
                for (int n = wid; n < N_; n += 16) {
                    float wwn = wwPer[n];
                    float m0 = memS[n*64+lane]    + wwn*(wv0 - er0);
                    float m1 = memS[n*64+lane+32] + wwn*(wv1 - er1);
                    memS[n*64+lane]    = m0;
                    memS[n*64+lane+32] = m1;
                    float ss = m0*m0 + m1*m1;
                    float c[4];
                    #pragma unroll
                    for (int r = 0; r < 4; r++) c[r] = m0*rka[r] + m1*rkb[r];
                    #pragma unroll
                    for (int o = 16; o; o >>= 1) {
                        ss += __shfl_xor_sync(FULL, ss, o);
                        c[0] += __shfl_xor_sync(FULL, c[0], o);
                        c[1] += __shfl_xor_sync(FULL, c[1], o);
                        c[2] += __shfl_xor_sync(FULL, c[2], o);
                        c[3] += __shfl_xor_sync(FULL, c[3], o);
                    }
                    if (lane == 0) {
                        float invn = 1.f/(sqrtf(ss) + 1e-6f);
                        #pragma unroll
                        for (int r = 0; r < 4; r++) crS[n*4+r] = c[r]*invn/rknr[r]*rsr[r];
                    }
                }
            }
            __syncthreads();

            // P5: links update + fwd walk + bwd partials (fused), 16 warps x 8 rows
            {
                float rj[4][4], pj[4], wwj[4], bw[4][4];
                #pragma unroll
                for (int q = 0; q < 4; q++) {
                    pj[q] = pPer[lane+32*q]; wwj[q] = wwPer[lane+32*q];
                    #pragma unroll
                    for (int r = 0; r < 4; r++) { rj[r][q] = rwoldT[r*128 + lane + 32*q]; bw[q][r] = 0.f; }
                }
                int i0 = wid * 8;
                for (int ii = 0; ii < 8; ii++) {
                    int i = i0 + ii;
                    float wi = wwPer[i];
                    float ri[4];
                    #pragma unroll
                    for (int r = 0; r < 4; r++) ri[r] = rwoldT[r*128 + i];
                    float f[4] = {0.f, 0.f, 0.f, 0.f};
                    #pragma unroll
                    for (int q = 0; q < 4; q++) {
                        int j = lane + 32*q;
                        float L = linkS[i*129 + j];
                        L = (1.f - wi - wwj[q])*L + wi*pj[q];
                        if (i == j) L = 0.f;
                        linkS[i*129 + j] = L;
                        #pragma unroll
                        for (int r = 0; r < 4; r++) {
                            f[r]     = fmaf(L, rj[r][q], f[r]);
                            bw[q][r] = fmaf(L, ri[r],    bw[q][r]);
                        }
                    }
                    #pragma unroll
                    for (int o = 16; o; o >>= 1) {
                        f[0] += __shfl_xor_sync(FULL, f[0], o);
                        f[1] += __shfl_xor_sync(FULL, f[1], o);
                        f[2] += __shfl_xor_sync(FULL, f[2], o);
                        f[3] += __shfl_xor_sync(FULL, f[3], o);
                    }
                    if (lane == 0) {
                        #pragma unroll
                        for (int r = 0; r < 4; r++) fwdS[i*4+r] = f[r];
                    }
                }
                #pragma unroll
                for (int q = 0; q < 4; q++)
                    #pragma unroll
                    for (int r = 0; r < 4; r++)
                        bwdP[wid*512 + (lane+32*q)*4 + r] = bw[q][r];
            }
            __syncthreads();

            // P6: cr softmax (warps 0-3) + bwd reduce over 16 partial sets (warps 4-7)
            if (wid < 4) {
                int r = wid;
                float m = -1e30f;
                #pragma unroll
                for (int q = 0; q < 4; q++) m = fmaxf(m, crS[(lane + 32*q)*4 + r]);
                #pragma unroll
                for (int o = 16; o; o >>= 1) m = fmaxf(m, __shfl_xor_sync(FULL, m, o));
                float s_ = 0.f;
                #pragma unroll
                for (int q = 0; q < 4; q++) s_ += expf(crS[(lane + 32*q)*4 + r] - m);
                #pragma unroll
                for (int o = 16; o; o >>= 1) s_ += __shfl_xor_sync(FULL, s_, o);
                if (lane == 0) { red[r*2] = m; red[r*2+1] = s_; }
            } else if (wid < 8) {
                int t2 = (wid - 4)*32 + lane;     // 0..127
                #pragma unroll
                for (int q = 0; q < 4; q++) {
                    int jr = t2 + 128*q;
                    float acc = 0.f;
                    #pragma unroll
                    for (int w16 = 0; w16 < 16; w16++) acc += bwdP[w16*512 + jr];
                    bwdS[jr] = acc;
                }
            }
            __syncthreads();

            // P7: new read weights
            if (tid < 128) {
                int n = tid;
                #pragma unroll
                for (int r = 0; r < 4; r++) {
                    float c = expf(crS[n*4+r] - red[r*2]) / red[r*2+1];
                    float v = rmS[r*3+0]*bwdS[n*4+r] + rmS[r*3+1]*c + rmS[r*3+2]*fwdS[n*4+r];
                    rwnewS[n*4+r] = v;
                }
            }
            __syncthreads();

            // P8: read vectors + rwold rotate
            if (tid < 256) {
                int w = tid >> 2, r = tid & 3;
                float acc = 0.f;
                #pragma unroll 8
                for (int n = 0; n < 128; n++) acc = fmaf(memS[n*64+w], rwnewS[n*4+r], acc);
                g_r[b*256 + w*4 + r] = acc;
                out[((size_t)t*B_ + b)*HR + 512 + w*4 + r] = acc;
            }
            rwoldT[(tid & 3)*128 + (tid >> 2)] = rwnewS[tid];
        }
        gbar(tgt);   // g_r visible for next gates
    }

    // ---- tail: copy hrs[-1] ----
    if (tid < 384) {
        int idx = bid*384 + tid;
        out[(size_t)T_*B_*HR + idx] = __ldcg(out + (size_t)(T_-1)*B_*HR + idx);
    }
}

extern "C" void kernel_launch(void* const* d_in, const int* in_sizes, int n_in,
                              void* d_out, int out_size) {
    const float* x    = (const float*)d_in[0];
    const float* M0   = (const float*)d_in[1];
    const float* W_ih = (const float*)d_in[2];
    const float* b_ih = (const float*)d_in[3];
    const float* W_hh = (const float*)d_in[4];
    const float* b_hh = (const float*)d_in[5];
    const float* Wrk  = (const float*)d_in[6];
    const float* brk  = (const float*)d_in[7];
    const float* Wrs  = (const float*)d_in[8];
    const float* brs  = (const float*)d_in[9];
    const float* Wwk  = (const float*)d_in[10];
    const float* bwk  = (const float*)d_in[11];
    const float* Wws  = (const float*)d_in[12];
    const float* bws  = (const float*)d_in[13];
    const float* We   = (const float*)d_in[14];
    const float* be   = (const float*)d_in[15];
    const float* Wv   = (const float*)d_in[16];
    const float* bv   = (const float*)d_in[17];
    const float* Wfg  = (const float*)d_in[18];
    const float* bfg  = (const float*)d_in[19];
    const float* Wag  = (const float*)d_in[20];
    const float* bag  = (const float*)d_in[21];
    const float* Wwg  = (const float*)d_in[22];
    const float* bwg  = (const float*)d_in[23];
    const float* Wrm  = (const float*)d_in[24];
    const float* brm  = (const float*)d_in[25];
    float* out = (float*)d_out;

    cudaFuncSetAttribute(k_dnc, cudaFuncAttributeMaxDynamicSharedMemorySize, SM_BYTES);

    k_init<<<128, 256>>>();
    k_dnc<<<GRID_, TPB_, SM_BYTES>>>(x, M0, W_ih, b_ih, W_hh, b_hh,
        Wrk, brk, Wrs, brs, Wwk, bwk, Wws, bws, We, be, Wv, bv,
        Wfg, bfg, Wag, bag, Wwg, bwg, Wrm, brm, out);
}

// round 8
// speedup vs baseline: 2.5369x; 1.0354x over previous
#include <cuda_runtime.h>
#include <math.h>
#include <stdint.h>
#include <stddef.h>

#define T_   128
#define B_   64
#define D_   256
#define H_   512
#define R_   4
#define N_   128
#define W_   64
#define HR   768
#define NIF  471
#define NIFP 480
#define GRID_ 128
#define TPB_  512

// ---------------- cross-block global state ----------------
__device__ __align__(16) float g_h[2][B_*H_];
__device__ __align__(16) float g_r[B_*R_*W_];
__device__ __align__(16) float g_if[B_*NIFP];
__device__ unsigned g_bar;

__device__ __forceinline__ float sigm(float x) { return 1.f/(1.f+expf(-x)); }
__device__ __forceinline__ float oneplus(float v) {
    float sp = (v > 20.f) ? v : log1pf(expf(v));
    return 1.f + sp;
}
__device__ __forceinline__ void fma2(unsigned long long &d, unsigned long long a, unsigned long long b) {
    asm("fma.rn.f32x2 %0, %1, %2, %3;" : "=l"(d) : "l"(a), "l"(b), "l"(d));
}
__device__ __forceinline__ float f2sum(unsigned long long v) {
    float lo = __uint_as_float((unsigned)(v & 0xffffffffull));
    float hi = __uint_as_float((unsigned)(v >> 32));
    return lo + hi;
}

// software grid barrier: all GRID_ blocks co-resident (1 CTA/SM via smem)
__device__ __forceinline__ void gbar(unsigned &tgt) {
    __syncthreads();
    if (threadIdx.x == 0) {
        __threadfence();
        atomicAdd(&g_bar, 1u);
        unsigned v;
        do {
            asm volatile("ld.acquire.gpu.u32 %0, [%1];" : "=r"(v) : "l"(&g_bar) : "memory");
            if (v < tgt) __nanosleep(20);
        } while (v < tgt);
    }
    __syncthreads();
    tgt += GRID_;
}

// ---------------- init ----------------
__global__ void k_init() {
    int i = blockIdx.x*blockDim.x + threadIdx.x;
    int stride = gridDim.x*blockDim.x;
    for (int idx = i; idx < 2*B_*H_; idx += stride) ((float*)g_h)[idx] = 0.f;
    for (int idx = i; idx < B_*R_*W_; idx += stride) g_r[idx] = 0.f;
    if (i == 0) g_bar = 0u;
}

// smem layout (floats)
#define OFF_LINK 0                         // [128][129] = 16512
#define OFF_MEM  16512                     // 8192
#define OFF_RWT  (16512+8192)              // rwoldT [r][n] 512
#define OFF_U    (OFF_RWT+512)             // 128
#define OFF_P    (OFF_U+128)               // 128
#define OFF_WW   (OFF_P+128)               // 128
#define OFF_S    (OFF_WW+128)              // sS 256 (LSTM cell state, 4 cols x 64 b)
#define OFF_SCR  (OFF_S+256)               // scratch union base
#define SCR_FLOATS 16128                   // gates: 3x4352 A + 3x1024 W; state: 11240; iface: 9736
#define SM_FLOATS (OFF_SCR + SCR_FLOATS)
#define SM_BYTES  (SM_FLOATS*4)

__global__ void __launch_bounds__(TPB_, 1) k_dnc(
    const float* __restrict__ x, const float* __restrict__ M0,
    const float* __restrict__ W_ih, const float* __restrict__ b_ih,
    const float* __restrict__ W_hh, const float* __restrict__ b_hh,
    const float* __restrict__ Wrk, const float* __restrict__ brk,
    const float* __restrict__ Wrs, const float* __restrict__ brs,
    const float* __restrict__ Wwk, const float* __restrict__ bwk,
    const float* __restrict__ Wws, const float* __restrict__ bws,
    const float* __restrict__ We,  const float* __restrict__ be,
    const float* __restrict__ Wv,  const float* __restrict__ bv,
    const float* __restrict__ Wfg, const float* __restrict__ bfg,
    const float* __restrict__ Wag, const float* __restrict__ bag,
    const float* __restrict__ Wwg, const float* __restrict__ bwg,
    const float* __restrict__ Wrm, const float* __restrict__ brm,
    float* __restrict__ out)
{
    extern __shared__ float sm[];
    float* linkS  = sm + OFF_LINK;
    float* memS   = sm + OFF_MEM;
    float* rwoldT = sm + OFF_RWT;
    float* uS     = sm + OFF_U;
    float* pPer   = sm + OFF_P;
    float* wwPer  = sm + OFF_WW;
    float* sS     = sm + OFF_S;
    float* scr    = sm + OFF_SCR;
    // state scratch (aliases gates/iface scratch)
    float* rwnewS= scr;          // 512 [n][r]
    float* crS   = scr + 512;    // 512
    float* fwdS  = scr + 1024;   // 512
    float* bwdS  = scr + 1536;   // 512
    float* bwdP  = scr + 2048;   // 8192 = 16 warps x 512
    float* suS   = scr + 10240;  // 128
    float* aAl   = scr + 10368;  // 128
    float* cwS   = scr + 10496;  // 128
    float* normM = scr + 10624;  // 128
    float* rkS   = scr + 10752;  // 256 [r][w]
    float* wkS   = scr + 11008;  // 64
    float* erS   = scr + 11072;  // 64
    float* wvS   = scr + 11136;  // 64
    float* fgS   = scr + 11200;  // 4
    float* rsS   = scr + 11204;  // 4
    float* rmS   = scr + 11208;  // 12
    float* rknS  = scr + 11220;  // 4
    float* scal  = scr + 11224;  // 8 (0:wkn 1:ws 2:ag 3:wg)
    float* red   = scr + 11232;  // 8

    const int tid  = threadIdx.x;
    const int lane = tid & 31, wid = tid >> 5;
    const int bid  = blockIdx.x;
    const unsigned FULL = 0xffffffffu;
    unsigned tgt = GRID_;
    const bool isStage = (tid >= 256);
    const int st = tid - 256;

    // ---- one-time smem init ----
    if (bid < 64) {
        for (int i = tid; i < N_*W_; i += TPB_) memS[i] = M0[i];
        for (int i = tid; i < 16512; i += TPB_) linkS[i] = 0.f;
        if (tid < 512) rwoldT[tid] = 0.f;
        if (tid < 128) { uS[tid] = 1e-6f; pPer[tid] = 0.f; wwPer[tid] = 0.f; }
    }
    if (tid < 256) sS[tid] = 0.f;
    __syncthreads();

    const int jbase = bid * 4;
    const int rg = (tid >> 6) & 3;   // compute threads: column group 0..3
    const int b2 = tid & 63;

    for (int t = 0; t < T_; t++) {
        // ================= gates phase (all 128 blocks) =================
        {
            const float* hprev = g_h[t & 1];
            float* aB0 = scr;            float* aB1 = scr + 4352;  float* aB2 = scr + 8704;
            float* wB0 = scr + 13056;    float* wB1 = scr + 14080; float* wB2 = scr + 15104;
            float* aBs[3] = {aB0, aB1, aB2};
            float* wBs[3] = {wB0, wB1, wB2};
            float4 aR[4]; float4 wR;

            auto gload = [&](int cc) {
                int k0 = cc * 64;
                const float* src; int strd;
                if (k0 < 256)      { src = x + (size_t)t*B_*D_ + k0; strd = D_; }
                else if (k0 < 512) { src = g_r + (k0-256);           strd = 256; }
                else               { src = hprev + (k0-512);         strd = H_; }
                #pragma unroll
                for (int q = 0; q < 4; q++) {
                    int f = st + 256*q;
                    int bb = f >> 4, k4 = f & 15;
                    aR[q] = __ldcg((const float4*)(src + (size_t)bb*strd + k4*4));
                }
                int row = st >> 4, k4 = st & 15;
                int cc2 = row >> 2, g = row & 3;
                int G = g*H_ + jbase + cc2;
                const float* wp = (k0 < 512) ? (W_ih + (size_t)G*512 + k0)
                                             : (W_hh + (size_t)G*512 + (k0-512));
                wR = *(const float4*)(wp + k4*4);
            };
            auto gstore = [&](int pb) {
                #pragma unroll
                for (int q = 0; q < 4; q++) {
                    int f = st + 256*q;
                    int bb = f >> 4, k4 = f & 15;
                    *(float4*)(aBs[pb] + bb*68 + k4*4) = aR[q];
                }
                int row = st >> 4, k4 = st & 15;
                *(float4*)(wBs[pb] + row*64 + k4*4) = wR;
            };

            if (isStage) { gload(0); gstore(0); gload(1); gstore(1); }
            unsigned long long acc0 = 0ull, acc1 = 0ull, acc2 = 0ull, acc3 = 0ull;
            __syncthreads();

            for (int c = 0; c < 16; c++) {
                if (isStage) {
                    if (c + 2 < 16) gload(c + 2);
                } else {
                    int pb = c % 3;
                    const ulonglong2* a2 = (const ulonglong2*)(aBs[pb] + b2*68);
                    const ulonglong2* w0 = (const ulonglong2*)(wBs[pb] + (rg*4+0)*64);
                    const ulonglong2* w1 = (const ulonglong2*)(wBs[pb] + (rg*4+1)*64);
                    const ulonglong2* w2 = (const ulonglong2*)(wBs[pb] + (rg*4+2)*64);
                    const ulonglong2* w3 = (const ulonglong2*)(wBs[pb] + (rg*4+3)*64);
                    #pragma unroll
                    for (int q = 0; q < 16; q++) {
                        ulonglong2 av = a2[q];
                        ulonglong2 v0 = w0[q], v1 = w1[q], v2 = w2[q], v3 = w3[q];
                        fma2(acc0, av.x, v0.x); fma2(acc0, av.y, v0.y);
                        fma2(acc1, av.x, v1.x); fma2(acc1, av.y, v1.y);
                        fma2(acc2, av.x, v2.x); fma2(acc2, av.y, v2.y);
                        fma2(acc3, av.x, v3.x); fma2(acc3, av.y, v3.y);
                    }
                }
                if (isStage && c + 2 < 16) gstore((c + 2) % 3);
                __syncthreads();
            }

            if (!isStage) {
                int j = jbase + rg;
                float gi = f2sum(acc0) + b_ih[0*H_+j] + b_hh[0*H_+j];
                float gf = f2sum(acc1) + b_ih[1*H_+j] + b_hh[1*H_+j];
                float gg = f2sum(acc2) + b_ih[2*H_+j] + b_hh[2*H_+j];
                float go = f2sum(acc3) + b_ih[3*H_+j] + b_hh[3*H_+j];
                float sold = sS[rg*64 + b2];
                float snew = sigm(gf)*sold + sigm(gi)*tanhf(gg);
                float hnew = sigm(go)*tanhf(snew);
                sS[rg*64 + b2] = snew;
                g_h[(t&1)^1][b2*H_ + j] = hnew;
                out[((size_t)t*B_ + b2)*HR + j] = hnew;
            }
        }
        gbar(tgt);   // h visible

        // ================= iface phase (blocks 0..58, 8 cols each) =================
        if (bid < 59) {
            const float* hcur = g_h[(t&1)^1];
            float* hB0 = scr;          float* hB1 = scr + 4352;
            float* wI0 = scr + 8704;   float* wI1 = scr + 9216;
            float* biasS = scr + 9728; // 8
            float* hBs[2] = {hB0, hB1};
            float* wIs[2] = {wI0, wI1};
            int Cbase = bid * 8;
            float4 hR[4]; float4 wiR;

            auto iload = [&](int cc) {
                int k0 = cc * 64;
                #pragma unroll
                for (int q = 0; q < 4; q++) {
                    int f = st + 256*q;
                    int bb = f >> 4, k4 = f & 15;
                    hR[q] = __ldcg((const float4*)(hcur + bb*H_ + k0 + k4*4));
                }
                if (st < 128) {
                    int row = st >> 4, k4 = st & 15;
                    int C = Cbase + row;
                    const float* wp = nullptr;
                    if (C < 256)       { int w = C>>2, r = C&3; wp = Wrk + ((size_t)r*W_ + w)*H_; }
                    else if (C < 260)  wp = Wrs + (C-256)*H_;
                    else if (C < 272)  wp = Wrm + (C-260)*H_;
                    else if (C < 276)  wp = Wfg + (C-272)*H_;
                    else if (C < 340)  wp = Wwk + (C-276)*H_;
                    else if (C == 340) wp = Wws;
                    else if (C < 405)  wp = We + (C-341)*H_;
                    else if (C < 469)  wp = Wv + (C-405)*H_;
                    else if (C == 469) wp = Wag;
                    else if (C == 470) wp = Wwg;
                    if (wp) wiR = *(const float4*)(wp + k0 + k4*4);
                    else    wiR = make_float4(0.f, 0.f, 0.f, 0.f);
                }
            };
            auto istore = [&](int pb) {
                #pragma unroll
                for (int q = 0; q < 4; q++) {
                    int f = st + 256*q;
                    int bb = f >> 4, k4 = f & 15;
                    *(float4*)(hBs[pb] + bb*68 + k4*4) = hR[q];
                }
                if (st < 128) {
                    int row = st >> 4, k4 = st & 15;
                    *(float4*)(wIs[pb] + row*64 + k4*4) = wiR;
                }
            };

            if (isStage) {
                iload(0); istore(0);
                if (st < 8) {
                    int C = Cbase + st; float bb = 0.f;
                    if (C < 256)       { int w = C>>2, r = C&3; bb = brk[r*W_ + w]; }
                    else if (C < 260)  bb = brs[C-256];
                    else if (C < 272)  bb = brm[C-260];
                    else if (C < 276)  bb = bfg[C-272];
                    else if (C < 340)  bb = bwk[C-276];
                    else if (C == 340) bb = bws[0];
                    else if (C < 405)  bb = be[C-341];
                    else if (C < 469)  bb = bv[C-405];
                    else if (C == 469) bb = bag[0];
                    else if (C == 470) bb = bwg[0];
                    biasS[st] = bb;
                }
            }
            unsigned long long acc0 = 0ull, acc1 = 0ull;
            __syncthreads();

            for (int c = 0; c < 8; c++) {
                if (isStage) {
                    if (c + 1 < 8) iload(c + 1);
                } else {
                    int pb = c & 1;
                    const ulonglong2* a2 = (const ulonglong2*)(hBs[pb] + b2*68);
                    const ulonglong2* w0 = (const ulonglong2*)(wIs[pb] + rg*64);
                    const ulonglong2* w1 = (const ulonglong2*)(wIs[pb] + (rg+4)*64);
                    #pragma unroll
                    for (int q = 0; q < 16; q++) {
                        ulonglong2 av = a2[q];
                        ulonglong2 v0 = w0[q], v1 = w1[q];
                        fma2(acc0, av.x, v0.x); fma2(acc0, av.y, v0.y);
                        fma2(acc1, av.x, v1.x); fma2(acc1, av.y, v1.y);
                    }
                }
                if (isStage && c + 1 < 8) istore((c + 1) & 1);
                __syncthreads();
            }

            if (!isStage) {
                int C0 = Cbase + rg;
                int C1 = Cbase + rg + 4;
                g_if[b2*NIFP + C0] = f2sum(acc0) + biasS[rg];
                if (C1 < NIF) g_if[b2*NIFP + C1] = f2sum(acc1) + biasS[rg+4];
            }
        }
        gbar(tgt);   // g_if visible

        // ================= state phase (blocks 0..63) =================
        if (bid < 64) {
            const int b = bid;
            const float* ifr = g_if + b*NIFP;

            // S0: interface unpack
            if (tid < 256) { int w = tid >> 2, r = tid & 3; rkS[r*64 + w] = __ldcg(ifr + tid); }
            else if (tid < 320) { int i = tid-256; wkS[i] = __ldcg(ifr + 276 + i); }
            else if (tid < 384) { int i = tid-320; erS[i] = sigm(__ldcg(ifr + 341 + i)); }
            else if (tid < 448) { int i = tid-384; wvS[i] = sigm(__ldcg(ifr + 405 + i)); }
            else if (tid < 452) {
                int i = tid-448;
                fgS[i] = sigm(__ldcg(ifr + 272 + i));
                rsS[i] = oneplus(__ldcg(ifr + 256 + i));
                float m0 = __ldcg(ifr+260+i*3+0), m1 = __ldcg(ifr+260+i*3+1), m2 = __ldcg(ifr+260+i*3+2);
                float mx = fmaxf(m0, fmaxf(m1, m2));
                float e0 = expf(m0-mx), e1 = expf(m1-mx), e2 = expf(m2-mx);
                float si = e0+e1+e2;
                rmS[i*3+0]=e0/si; rmS[i*3+1]=e1/si; rmS[i*3+2]=e2/si;
            }
            else if (tid == 500) {
                scal[1] = oneplus(__ldcg(ifr + 340));
                scal[2] = sigm(__ldcg(ifr + 469));
                scal[3] = sigm(__ldcg(ifr + 470));
            }
            __syncthreads();

            // P1: old mem norms, key norms, usage
            for (int n = wid; n < N_; n += 16) {
                float v0 = memS[n*64+lane], v1 = memS[n*64+lane+32];
                float ss = v0*v0 + v1*v1;
                #pragma unroll
                for (int o = 16; o; o >>= 1) ss += __shfl_xor_sync(FULL, ss, o);
                if (lane == 0) normM[n] = sqrtf(ss);
            }
            if (wid == 0) {
                float v = wkS[lane]*wkS[lane] + wkS[lane+32]*wkS[lane+32];
                #pragma unroll
                for (int o = 16; o; o >>= 1) v += __shfl_xor_sync(FULL, v, o);
                if (lane == 0) scal[0] = sqrtf(v);
            }
            if (wid >= 1 && wid <= 4) {
                int r = wid - 1;
                float a0 = rkS[r*64+lane], a1 = rkS[r*64+lane+32];
                float ss = a0*a0 + a1*a1;
                #pragma unroll
                for (int o = 16; o; o >>= 1) ss += __shfl_xor_sync(FULL, ss, o);
                if (lane == 0) rknS[r] = sqrtf(ss);
            }
            if (tid < 128) {
                float psi = (1.f - fgS[0]*rwoldT[0*128+tid]) * (1.f - fgS[1]*rwoldT[1*128+tid])
                          * (1.f - fgS[2]*rwoldT[2*128+tid]) * (1.f - fgS[3]*rwoldT[3*128+tid]);
                float uo = uS[tid], wo = wwPer[tid];
                float un = (uo + wo - uo*wo) * psi;
                suS[tid] = un;
                uS[tid] = un;
            }
            __syncthreads();

            // P2: warp0 sort+scan+alloc; warps 1-15 content write scores
            if (wid == 0) {
                float v[4];
                #pragma unroll
                for (int s = 0; s < 4; s++) v[s] = suS[s*32 + lane];
                #pragma unroll
                for (int k = 2; k <= 128; k <<= 1) {
                    for (int j = k >> 1; j >= 32; j >>= 1) {
                        int js = j >> 5;
                        #pragma unroll
                        for (int s = 0; s < 4; s++) if (!(s & js)) {
                            int sp = s | js;
                            bool up = (((s*32 + lane) & k) == 0);
                            float lo = v[s], hi = v[sp];
                            float mn = fminf(lo, hi), mx = fmaxf(lo, hi);
                            v[s]  = up ? mn : mx;
                            v[sp] = up ? mx : mn;
                        }
                    }
                    for (int j = ((k>>1) > 16 ? 16 : (k>>1)); j >= 1; j >>= 1) {
                        #pragma unroll
                        for (int s = 0; s < 4; s++) {
                            bool up = (((s*32 + lane) & k) == 0);
                            float o = __shfl_xor_sync(FULL, v[s], j);
                            bool lower = ((lane & j) == 0);
                            v[s] = (up == lower) ? fminf(v[s], o) : fmaxf(v[s], o);
                        }
                    }
                }
                #pragma unroll
                for (int s = 0; s < 4; s++) suS[s*32 + lane] = v[s];
                __syncwarp();
                float w0 = suS[lane*4+0], w1 = suS[lane*4+1], w2 = suS[lane*4+2], w3 = suS[lane*4+3];
                float pl = w0*w1*w2*w3;
                float incl = pl;
                #pragma unroll
                for (int off = 1; off < 32; off <<= 1) {
                    float tv = __shfl_up_sync(FULL, incl, off);
                    if (lane >= off) incl *= tv;
                }
                float base = __shfl_up_sync(FULL, incl, 1);
                if (lane == 0) base = 1.f;
                float run = base;
                aAl[lane*4+0] = (1.f - w0)*run; run *= w0;
                aAl[lane*4+1] = (1.f - w1)*run; run *= w1;
                aAl[lane*4+2] = (1.f - w2)*run; run *= w2;
                aAl[lane*4+3] = (1.f - w3)*run;
            } else {
                float wkn = scal[0], ws = scal[1];
                float k0 = wkS[lane], k1 = wkS[lane+32];
                for (int n = wid - 1; n < N_; n += 15) {
                    float d = memS[n*64+lane]*k0 + memS[n*64+lane+32]*k1;
                    #pragma unroll
                    for (int o = 16; o; o >>= 1) d += __shfl_xor_sync(FULL, d, o);
                    if (lane == 0) cwS[n] = d / ((normM[n] + 1e-6f) * wkn) * ws;
                }
            }
            __syncthreads();

            // P3: warp0: cw softmax -> ww -> sum -> precedence
            if (wid == 0) {
                float c0 = cwS[lane*4+0], c1 = cwS[lane*4+1], c2 = cwS[lane*4+2], c3 = cwS[lane*4+3];
                float mx = fmaxf(fmaxf(c0,c1), fmaxf(c2,c3));
                #pragma unroll
                for (int o = 16; o; o >>= 1) mx = fmaxf(mx, __shfl_xor_sync(FULL, mx, o));
                float e0 = expf(c0-mx), e1 = expf(c1-mx), e2 = expf(c2-mx), e3 = expf(c3-mx);
                float sme = e0+e1+e2+e3;
                #pragma unroll
                for (int o = 16; o; o >>= 1) sme += __shfl_xor_sync(FULL, sme, o);
                float inv = 1.f/sme;
                float ag = scal[2], wg = scal[3];
                float ww0 = wg*(ag*aAl[lane*4+0] + (1.f-ag)*e0*inv);
                float ww1 = wg*(ag*aAl[lane*4+1] + (1.f-ag)*e1*inv);
                float ww2 = wg*(ag*aAl[lane*4+2] + (1.f-ag)*e2*inv);
                float ww3 = wg*(ag*aAl[lane*4+3] + (1.f-ag)*e3*inv);
                wwPer[lane*4+0]=ww0; wwPer[lane*4+1]=ww1; wwPer[lane*4+2]=ww2; wwPer[lane*4+3]=ww3;
                float S = ww0+ww1+ww2+ww3;
                #pragma unroll
                for (int o = 16; o; o >>= 1) S += __shfl_xor_sync(FULL, S, o);
                float oms = 1.f - S;
                pPer[lane*4+0] = oms*pPer[lane*4+0] + ww0;
                pPer[lane*4+1] = oms*pPer[lane*4+1] + ww1;
                pPer[lane*4+2] = oms*pPer[lane*4+2] + ww2;
                pPer[lane*4+3] = oms*pPer[lane*4+3] + ww3;
            }
            __syncthreads();

            // P4: mem write + new norm + content-read scores (fused)
            {
                float er0 = erS[lane], er1 = erS[lane+32];
                float wv0 = wvS[lane], wv1 = wvS[lane+32];
                float rka[4], rkb[4], rsr[4], rknr[4];
                #pragma unroll
                for (int r = 0; r < 4; r++) {
                    rka[r] = rkS[r*64+lane]; rkb[r] = rkS[r*64+lane+32];
                    rsr[r] = rsS[r]; rknr[r] = rknS[r];
                }
                for (int n = wid; n < N_; n += 16) {
                    float wwn = wwPer[n];
                    float m0 = memS[n*64+lane]    + wwn*(wv0 - er0);
                    float m1 = memS[n*64+lane+32] + wwn*(wv1 - er1);
                    memS[n*64+lane]    = m0;
                    memS[n*64+lane+32] = m1;
                    float ss = m0*m0 + m1*m1;
                    float c[4];
                    #pragma unroll
                    for (int r = 0; r < 4; r++) c[r] = m0*rka[r] + m1*rkb[r];
                    #pragma unroll
                    for (int o = 16; o; o >>= 1) {
                        ss += __shfl_xor_sync(FULL, ss, o);
                        c[0] += __shfl_xor_sync(FULL, c[0], o);
                        c[1] += __shfl_xor_sync(FULL, c[1], o);
                        c[2] += __shfl_xor_sync(FULL, c[2], o);
                        c[3] += __shfl_xor_sync(FULL, c[3], o);
                    }
                    if (lane == 0) {
                        float invn = 1.f/(sqrtf(ss) + 1e-6f);
                        #pragma unroll
                        for (int r = 0; r < 4; r++) crS[n*4+r] = c[r]*invn/rknr[r]*rsr[r];
                    }
                }
            }
            __syncthreads();

            // P5: links update + fwd walk + bwd partials (fused), 16 warps x 8 rows
            {
                float rj[4][4], pj[4], wwj[4], bw[4][4];
                #pragma unroll
                for (int q = 0; q < 4; q++) {
                    pj[q] = pPer[lane+32*q]; wwj[q] = wwPer[lane+32*q];
                    #pragma unroll
                    for (int r = 0; r < 4; r++) { rj[r][q] = rwoldT[r*128 + lane + 32*q]; bw[q][r] = 0.f; }
                }
                int i0 = wid * 8;
                for (int ii = 0; ii < 8; ii++) {
                    int i = i0 + ii;
                    float wi = wwPer[i];
                    float ri[4];
                    #pragma unroll
                    for (int r = 0; r < 4; r++) ri[r] = rwoldT[r*128 + i];
                    float f[4] = {0.f, 0.f, 0.f, 0.f};
                    #pragma unroll
                    for (int q = 0; q < 4; q++) {
                        int j = lane + 32*q;
                        float L = linkS[i*129 + j];
                        L = (1.f - wi - wwj[q])*L + wi*pj[q];
                        if (i == j) L = 0.f;
                        linkS[i*129 + j] = L;
                        #pragma unroll
                        for (int r = 0; r < 4; r++) {
                            f[r]     = fmaf(L, rj[r][q], f[r]);
                            bw[q][r] = fmaf(L, ri[r],    bw[q][r]);
                        }
                    }
                    #pragma unroll
                    for (int o = 16; o; o >>= 1) {
                        f[0] += __shfl_xor_sync(FULL, f[0], o);
                        f[1] += __shfl_xor_sync(FULL, f[1], o);
                        f[2] += __shfl_xor_sync(FULL, f[2], o);
                        f[3] += __shfl_xor_sync(FULL, f[3], o);
                    }
                    if (lane == 0) {
                        #pragma unroll
                        for (int r = 0; r < 4; r++) fwdS[i*4+r] = f[r];
                    }
                }
                #pragma unroll
                for (int q = 0; q < 4; q++)
                    #pragma unroll
                    for (int r = 0; r < 4; r++)
                        bwdP[wid*512 + (lane+32*q)*4 + r] = bw[q][r];
            }
            __syncthreads();

            // P6: cr softmax (warps 0-3) + bwd reduce (warps 4-7)
            if (wid < 4) {
                int r = wid;
                float m = -1e30f;
                #pragma unroll
                for (int q = 0; q < 4; q++) m = fmaxf(m, crS[(lane + 32*q)*4 + r]);
                #pragma unroll
                for (int o = 16; o; o >>= 1) m = fmaxf(m, __shfl_xor_sync(FULL, m, o));
                float s_ = 0.f;
                #pragma unroll
                for (int q = 0; q < 4; q++) s_ += expf(crS[(lane + 32*q)*4 + r] - m);
                #pragma unroll
                for (int o = 16; o; o >>= 1) s_ += __shfl_xor_sync(FULL, s_, o);
                if (lane == 0) { red[r*2] = m; red[r*2+1] = s_; }
            } else if (wid < 8) {
                int t2 = (wid - 4)*32 + lane;
                #pragma unroll
                for (int q = 0; q < 4; q++) {
                    int jr = t2 + 128*q;
                    float acc = 0.f;
                    #pragma unroll
                    for (int w16 = 0; w16 < 16; w16++) acc += bwdP[w16*512 + jr];
                    bwdS[jr] = acc;
                }
            }
            __syncthreads();

            // P7: new read weights
            if (tid < 128) {
                int n = tid;
                #pragma unroll
                for (int r = 0; r < 4; r++) {
                    float c = expf(crS[n*4+r] - red[r*2]) / red[r*2+1];
                    float v = rmS[r*3+0]*bwdS[n*4+r] + rmS[r*3+1]*c + rmS[r*3+2]*fwdS[n*4+r];
                    rwnewS[n*4+r] = v;
                }
            }
            __syncthreads();

            // P8: read vectors + rwold rotate
            if (tid < 256) {
                int w = tid >> 2, r = tid & 3;
                float acc = 0.f;
                #pragma unroll 8
                for (int n = 0; n < 128; n++) acc = fmaf(memS[n*64+w], rwnewS[n*4+r], acc);
                g_r[b*256 + w*4 + r] = acc;
                out[((size_t)t*B_ + b)*HR + 512 + w*4 + r] = acc;
            }
            rwoldT[(tid & 3)*128 + (tid >> 2)] = rwnewS[tid];
        }
        gbar(tgt);   // g_r visible for next gates
    }

    // ---- tail: copy hrs[-1] ----
    if (tid < 384) {
        int idx = bid*384 + tid;
        out[(size_t)T_*B_*HR + idx] = __ldcg(out + (size_t)(T_-1)*B_*HR + idx);
    }
}

extern "C" void kernel_launch(void* const* d_in, const int* in_sizes, int n_in,
                              void* d_out, int out_size) {
    const float* x    = (const float*)d_in[0];
    const float* M0   = (const float*)d_in[1];
    const float* W_ih = (const float*)d_in[2];
    const float* b_ih = (const float*)d_in[3];
    const float* W_hh = (const float*)d_in[4];
    const float* b_hh = (const float*)d_in[5];
    const float* Wrk  = (const float*)d_in[6];
    const float* brk  = (const float*)d_in[7];
    const float* Wrs  = (const float*)d_in[8];
    const float* brs  = (const float*)d_in[9];
    const float* Wwk  = (const float*)d_in[10];
    const float* bwk  = (const float*)d_in[11];
    const float* Wws  = (const float*)d_in[12];
    const float* bws  = (const float*)d_in[13];
    const float* We   = (const float*)d_in[14];
    const float* be   = (const float*)d_in[15];
    const float* Wv   = (const float*)d_in[16];
    const float* bv   = (const float*)d_in[17];
    const float* Wfg  = (const float*)d_in[18];
    const float* bfg  = (const float*)d_in[19];
    const float* Wag  = (const float*)d_in[20];
    const float* bag  = (const float*)d_in[21];
    const float* Wwg  = (const float*)d_in[22];
    const float* bwg  = (const float*)d_in[23];
    const float* Wrm  = (const float*)d_in[24];
    const float* brm  = (const float*)d_in[25];
    float* out = (float*)d_out;

    cudaFuncSetAttribute(k_dnc, cudaFuncAttributeMaxDynamicSharedMemorySize, SM_BYTES);

    k_init<<<128, 256>>>();
    k_dnc<<<GRID_, TPB_, SM_BYTES>>>(x, M0, W_ih, b_ih, W_hh, b_hh,
        Wrk, brk, Wrs, brs, Wwk, bwk, Wws, bws, We, be, Wv, bv,
        Wfg, bfg, Wag, bag, Wwg, bwg, Wrm, brm, out);
}

// round 9
// speedup vs baseline: 2.7531x; 1.0852x over previous
#include <cuda_runtime.h>
#include <math.h>
#include <stdint.h>
#include <stddef.h>

#define T_   128
#define B_   64
#define D_   256
#define H_   512
#define R_   4
#define N_   128
#define W_   64
#define HR   768
#define NIF  471
#define NIFP 480
#define GRID_ 128
#define TPB_  512

// ---------------- cross-block global state ----------------
__device__ __align__(16) float g_h[2][B_*H_];
__device__ __align__(16) float g_r[B_*R_*W_];
__device__ __align__(16) float g_if[B_*NIFP];
__device__ unsigned g_bar;

__device__ __forceinline__ float sigm(float x) { return 1.f/(1.f+expf(-x)); }
__device__ __forceinline__ float oneplus(float v) {
    float sp = (v > 20.f) ? v : log1pf(expf(v));
    return 1.f + sp;
}
__device__ __forceinline__ void fma2(unsigned long long &d, unsigned long long a, unsigned long long b) {
    asm("fma.rn.f32x2 %0, %1, %2, %3;" : "=l"(d) : "l"(a), "l"(b), "l"(d));
}
__device__ __forceinline__ float f2sum(unsigned long long v) {
    float lo = __uint_as_float((unsigned)(v & 0xffffffffull));
    float hi = __uint_as_float((unsigned)(v >> 32));
    return lo + hi;
}
#define CP_CG(dst, src) asm volatile("cp.async.cg.shared.global [%0], [%1], 16;" :: "r"(dst), "l"(src))
#define CP_CA(dst, src) asm volatile("cp.async.ca.shared.global [%0], [%1], 16;" :: "r"(dst), "l"(src))
#define CP_COMMIT()     asm volatile("cp.async.commit_group;")
#define CP_WAIT1()      asm volatile("cp.async.wait_group 1;")
#define CP_WAIT0()      asm volatile("cp.async.wait_group 0;")

__device__ __forceinline__ void gbar(unsigned &tgt) {
    __syncthreads();
    if (threadIdx.x == 0) {
        __threadfence();
        atomicAdd(&g_bar, 1u);
        unsigned v;
        do {
            asm volatile("ld.acquire.gpu.u32 %0, [%1];" : "=r"(v) : "l"(&g_bar) : "memory");
            if (v < tgt) __nanosleep(20);
        } while (v < tgt);
    }
    __syncthreads();
    tgt += GRID_;
}

__global__ void k_init() {
    int i = blockIdx.x*blockDim.x + threadIdx.x;
    int stride = gridDim.x*blockDim.x;
    for (int idx = i; idx < 2*B_*H_; idx += stride) ((float*)g_h)[idx] = 0.f;
    for (int idx = i; idx < B_*R_*W_; idx += stride) g_r[idx] = 0.f;
    if (i == 0) g_bar = 0u;
}

// smem layout (floats)
#define LNK 132                             // links row stride (float4-aligned)
#define OFF_LINK 0                          // 128*132 = 16896
#define OFF_MEM  16896                      // 8192
#define OFF_RWN  (16896+8192)               // rwoldN [n][r] 512
#define OFF_RWT  (OFF_RWN+512)              // rwoldT [r][n] 512
#define OFF_U    (OFF_RWT+512)              // 128
#define OFF_P    (OFF_U+128)                // 128
#define OFF_WW   (OFF_P+128)                // 128
#define OFF_S    (OFF_WW+128)               // 256 LSTM cell state
#define OFF_NORM (OFF_S+256)                // 128 persistent row norms
#define OFF_SCR  (OFF_NORM+128)
#define SCR_FLOATS 16128
#define SM_FLOATS (OFF_SCR + SCR_FLOATS)
#define SM_BYTES  (SM_FLOATS*4)

__global__ void __launch_bounds__(TPB_, 1) k_dnc(
    const float* __restrict__ x, const float* __restrict__ M0,
    const float* __restrict__ W_ih, const float* __restrict__ b_ih,
    const float* __restrict__ W_hh, const float* __restrict__ b_hh,
    const float* __restrict__ Wrk, const float* __restrict__ brk,
    const float* __restrict__ Wrs, const float* __restrict__ brs,
    const float* __restrict__ Wwk, const float* __restrict__ bwk,
    const float* __restrict__ Wws, const float* __restrict__ bws,
    const float* __restrict__ We,  const float* __restrict__ be,
    const float* __restrict__ Wv,  const float* __restrict__ bv,
    const float* __restrict__ Wfg, const float* __restrict__ bfg,
    const float* __restrict__ Wag, const float* __restrict__ bag,
    const float* __restrict__ Wwg, const float* __restrict__ bwg,
    const float* __restrict__ Wrm, const float* __restrict__ brm,
    float* __restrict__ out)
{
    extern __shared__ float sm[];
    float* linkS  = sm + OFF_LINK;
    float* memS   = sm + OFF_MEM;
    float* rwoldN = sm + OFF_RWN;
    float* rwoldT = sm + OFF_RWT;
    float* uS     = sm + OFF_U;
    float* pPer   = sm + OFF_P;
    float* wwPer  = sm + OFF_WW;
    float* sS     = sm + OFF_S;
    float* normM  = sm + OFF_NORM;
    float* scr    = sm + OFF_SCR;
    // state scratch
    float* rwnewS= scr;          // 512
    float* crS   = scr + 512;    // 512
    float* fwdS  = scr + 1024;   // 512
    float* bwdS  = scr + 1536;   // 512
    float* bwdP  = scr + 2048;   // 8192
    float* suS   = scr + 10240;  // 128
    float* aAl   = scr + 10368;  // 128
    float* cwS   = scr + 10496;  // 128
    float* normP = scr + 10624;  // 512
    float* rkS   = scr + 11136;  // 256
    float* wkS   = scr + 11392;  // 64
    float* erS   = scr + 11456;  // 64
    float* wvS   = scr + 11520;  // 64
    float* fgS   = scr + 11584;  // 4
    float* rsS   = scr + 11588;  // 4
    float* rmS   = scr + 11592;  // 12
    float* rknS  = scr + 11604;  // 4
    float* scal  = scr + 11608;  // 8
    float* red   = scr + 11616;  // 8
    float* gpart = scr;          // gates partials [4][16][64] aliases aB0

    const int tid  = threadIdx.x;
    const int lane = tid & 31, wid = tid >> 5;
    const int bid  = blockIdx.x;
    const unsigned FULL = 0xffffffffu;
    unsigned tgt = GRID_;

    uint32_t smemU32;
    asm("{ .reg .u64 t0; cvta.to.shared.u64 t0, %1; cvt.u32.u64 %0, t0; }" : "=r"(smemU32) : "l"(sm));

    // ---- one-time smem init ----
    if (bid < 64) {
        for (int i = tid; i < N_*W_; i += TPB_) memS[i] = M0[i];
        for (int i = tid; i < N_*LNK; i += TPB_) linkS[i] = 0.f;
        if (tid < 512) { rwoldN[tid] = 0.f; rwoldT[tid] = 0.f; }
        if (tid < 128) { uS[tid] = 1e-6f; pPer[tid] = 0.f; wwPer[tid] = 0.f; }
    }
    if (tid < 256) sS[tid] = 0.f;
    __syncthreads();
    if (bid < 64 && tid < 128) {
        float ss = 0.f;
        for (int k = 0; k < 64; k++) { float v = memS[tid*64+k]; ss += v*v; }
        normM[tid] = sqrtf(ss);
    }
    __syncthreads();

    const int jbase = bid * 4;
    // gates compute decomposition
    const int kh  = tid >> 7;          // 0..3 (k quarter), uniform per warp
    const int jj  = (tid & 127) >> 5;  // 0..3 column, uniform per warp
    const int bp  = lane;              // batch pair {bp, bp+32}

    for (int t = 0; t < T_; t++) {
        // ================= gates phase (all 128 blocks, all warps compute) =================
        {
            const float* hprev = g_h[t & 1];
            float* aBs[3] = {scr, scr + 4352, scr + 8704};
            float* wBs[3] = {scr + 13056, scr + 14080, scr + 15104};

            auto gstage = [&](int cc) {
                int pb = cc % 3;
                int k0 = cc * 64;
                const float* src; size_t strd;
                if (k0 < 256)      { src = x + (size_t)t*B_*D_ + k0; strd = D_; }
                else if (k0 < 512) { src = g_r + (k0-256);           strd = 256; }
                else               { src = hprev + (k0-512);         strd = H_; }
                uint32_t aDst = smemU32 + (uint32_t)(OFF_SCR + pb*4352)*4u;
                int f0 = tid, f1 = tid + 512;
                CP_CG(aDst + (uint32_t)((f0>>4)*68 + (f0&15)*4)*4u, src + (size_t)(f0>>4)*strd + (f0&15)*4);
                CP_CG(aDst + (uint32_t)((f1>>4)*68 + (f1&15)*4)*4u, src + (size_t)(f1>>4)*strd + (f1&15)*4);
                if (tid < 256) {
                    int row = tid >> 4, k4 = tid & 15;
                    int j2 = row >> 2, g = row & 3;
                    int G = g*H_ + jbase + j2;
                    const float* wp = (k0 < 512) ? (W_ih + (size_t)G*512 + k0)
                                                 : (W_hh + (size_t)G*512 + (k0-512));
                    uint32_t wDst = smemU32 + (uint32_t)(OFF_SCR + 13056 + pb*1024 + row*64 + k4*4)*4u;
                    CP_CA(wDst, wp + k4*4);
                }
                CP_COMMIT();
            };

            gstage(0); gstage(1);
            unsigned long long acc0[4] = {0,0,0,0};   // batch bp
            unsigned long long acc1[4] = {0,0,0,0};   // batch bp+32

            for (int c = 0; c < 16; c++) {
                if (c < 15) { CP_WAIT1(); } else { CP_WAIT0(); }
                __syncthreads();
                if (c + 2 < 16) gstage(c + 2);
                int pb = c % 3;
                const float* aB = aBs[pb];
                const float* wB = wBs[pb];
                const ulonglong2* a0 = (const ulonglong2*)(aB + bp*68 + kh*16);
                const ulonglong2* a1 = (const ulonglong2*)(aB + (bp+32)*68 + kh*16);
                ulonglong2 A0[4], A1[4];
                #pragma unroll
                for (int q = 0; q < 4; q++) { A0[q] = a0[q]; A1[q] = a1[q]; }
                #pragma unroll
                for (int g = 0; g < 4; g++) {
                    const ulonglong2* w = (const ulonglong2*)(wB + (jj*4+g)*64 + kh*16);
                    #pragma unroll
                    for (int q = 0; q < 4; q++) {
                        ulonglong2 wv = w[q];
                        fma2(acc0[g], A0[q].x, wv.x); fma2(acc0[g], A0[q].y, wv.y);
                        fma2(acc1[g], A1[q].x, wv.x); fma2(acc1[g], A1[q].y, wv.y);
                    }
                }
            }
            __syncthreads();   // last buffers free before gpart overwrite
            #pragma unroll
            for (int g = 0; g < 4; g++) {
                gpart[kh*1024 + (jj*4+g)*64 + bp]      = f2sum(acc0[g]);
                gpart[kh*1024 + (jj*4+g)*64 + bp + 32] = f2sum(acc1[g]);
            }
            __syncthreads();
            if (tid < 256) {
                int j2 = tid >> 6, b3 = tid & 63;
                int j = jbase + j2;
                float gv[4];
                #pragma unroll
                for (int g = 0; g < 4; g++) {
                    float s_ = 0.f;
                    #pragma unroll
                    for (int k2 = 0; k2 < 4; k2++) s_ += gpart[k2*1024 + (j2*4+g)*64 + b3];
                    gv[g] = s_ + b_ih[g*H_+j] + b_hh[g*H_+j];
                }
                float sold = sS[j2*64 + b3];
                float snew = sigm(gv[1])*sold + sigm(gv[0])*tanhf(gv[2]);
                float hnew = sigm(gv[3])*tanhf(snew);
                sS[j2*64 + b3] = snew;
                g_h[(t&1)^1][b3*H_ + j] = hnew;
                out[((size_t)t*B_ + b3)*HR + j] = hnew;
            }
        }
        gbar(tgt);   // h visible

        // ================= iface phase (blocks 0..58, 8 cols each) =================
        if (bid < 59) {
            const float* hcur = g_h[(t&1)^1];
            const bool isStage = (tid >= 256);
            const int st = tid - 256;
            const int rg = (tid >> 6) & 3;
            const int b2 = tid & 63;
            float* hB0 = scr;          float* hB1 = scr + 4352;
            float* wI0 = scr + 8704;   float* wI1 = scr + 9216;
            float* biasS = scr + 9728;
            float* hBs[2] = {hB0, hB1};
            float* wIs[2] = {wI0, wI1};
            int Cbase = bid * 8;
            float4 hR[4]; float4 wiR;

            auto iload = [&](int cc) {
                int k0 = cc * 64;
                #pragma unroll
                for (int q = 0; q < 4; q++) {
                    int f = st + 256*q;
                    int bb = f >> 4, k4 = f & 15;
                    hR[q] = __ldcg((const float4*)(hcur + bb*H_ + k0 + k4*4));
                }
                if (st < 128) {
                    int row = st >> 4, k4 = st & 15;
                    int C = Cbase + row;
                    const float* wp = nullptr;
                    if (C < 256)       { int w = C>>2, r = C&3; wp = Wrk + ((size_t)r*W_ + w)*H_; }
                    else if (C < 260)  wp = Wrs + (C-256)*H_;
                    else if (C < 272)  wp = Wrm + (C-260)*H_;
                    else if (C < 276)  wp = Wfg + (C-272)*H_;
                    else if (C < 340)  wp = Wwk + (C-276)*H_;
                    else if (C == 340) wp = Wws;
                    else if (C < 405)  wp = We + (C-341)*H_;
                    else if (C < 469)  wp = Wv + (C-405)*H_;
                    else if (C == 469) wp = Wag;
                    else if (C == 470) wp = Wwg;
                    if (wp) wiR = *(const float4*)(wp + k0 + k4*4);
                    else    wiR = make_float4(0.f, 0.f, 0.f, 0.f);
                }
            };
            auto istore = [&](int pb) {
                #pragma unroll
                for (int q = 0; q < 4; q++) {
                    int f = st + 256*q;
                    int bb = f >> 4, k4 = f & 15;
                    *(float4*)(hBs[pb] + bb*68 + k4*4) = hR[q];
                }
                if (st < 128) {
                    int row = st >> 4, k4 = st & 15;
                    *(float4*)(wIs[pb] + row*64 + k4*4) = wiR;
                }
            };

            if (isStage) {
                iload(0); istore(0);
                if (st < 8) {
                    int C = Cbase + st; float bb = 0.f;
                    if (C < 256)       { int w = C>>2, r = C&3; bb = brk[r*W_ + w]; }
                    else if (C < 260)  bb = brs[C-256];
                    else if (C < 272)  bb = brm[C-260];
                    else if (C < 276)  bb = bfg[C-272];
                    else if (C < 340)  bb = bwk[C-276];
                    else if (C == 340) bb = bws[0];
                    else if (C < 405)  bb = be[C-341];
                    else if (C < 469)  bb = bv[C-405];
                    else if (C == 469) bb = bag[0];
                    else if (C == 470) bb = bwg[0];
                    biasS[st] = bb;
                }
            }
            unsigned long long acc0 = 0ull, acc1 = 0ull;
            __syncthreads();

            for (int c = 0; c < 8; c++) {
                if (isStage) {
                    if (c + 1 < 8) iload(c + 1);
                } else {
                    int pb = c & 1;
                    const ulonglong2* a2 = (const ulonglong2*)(hBs[pb] + b2*68);
                    const ulonglong2* w0 = (const ulonglong2*)(wIs[pb] + rg*64);
                    const ulonglong2* w1 = (const ulonglong2*)(wIs[pb] + (rg+4)*64);
                    #pragma unroll
                    for (int q = 0; q < 16; q++) {
                        ulonglong2 av = a2[q];
                        ulonglong2 v0 = w0[q], v1 = w1[q];
                        fma2(acc0, av.x, v0.x); fma2(acc0, av.y, v0.y);
                        fma2(acc1, av.x, v1.x); fma2(acc1, av.y, v1.y);
                    }
                }
                if (isStage && c + 1 < 8) istore((c + 1) & 1);
                __syncthreads();
            }

            if (!isStage) {
                int C0 = Cbase + rg;
                int C1 = Cbase + rg + 4;
                g_if[b2*NIFP + C0] = f2sum(acc0) + biasS[rg];
                if (C1 < NIF) g_if[b2*NIFP + C1] = f2sum(acc1) + biasS[rg+4];
            }
        }
        gbar(tgt);   // g_if visible

        // ================= state phase (blocks 0..63) =================
        if (bid < 64) {
            const int b = bid;
            const float* ifr = g_if + b*NIFP;
            const int n4 = tid >> 2, r4 = tid & 3;

            // S0: interface unpack
            if (tid < 256) { int w = tid >> 2, r = tid & 3; rkS[r*64 + w] = __ldcg(ifr + tid); }
            else if (tid < 320) { int i = tid-256; wkS[i] = __ldcg(ifr + 276 + i); }
            else if (tid < 384) { int i = tid-320; erS[i] = sigm(__ldcg(ifr + 341 + i)); }
            else if (tid < 448) { int i = tid-384; wvS[i] = sigm(__ldcg(ifr + 405 + i)); }
            else if (tid < 452) {
                int i = tid-448;
                fgS[i] = sigm(__ldcg(ifr + 272 + i));
                rsS[i] = oneplus(__ldcg(ifr + 256 + i));
                float m0 = __ldcg(ifr+260+i*3+0), m1 = __ldcg(ifr+260+i*3+1), m2 = __ldcg(ifr+260+i*3+2);
                float mx = fmaxf(m0, fmaxf(m1, m2));
                float e0 = expf(m0-mx), e1 = expf(m1-mx), e2 = expf(m2-mx);
                float si = e0+e1+e2;
                rmS[i*3+0]=e0/si; rmS[i*3+1]=e1/si; rmS[i*3+2]=e2/si;
            }
            else if (tid == 500) {
                scal[1] = oneplus(__ldcg(ifr + 340));
                scal[2] = sigm(__ldcg(ifr + 469));
                scal[3] = sigm(__ldcg(ifr + 470));
            }
            __syncthreads();

            // P1: key norms (shfl, small) + psi/usage
            if (wid == 0) {
                float v = wkS[lane]*wkS[lane] + wkS[lane+32]*wkS[lane+32];
                #pragma unroll
                for (int o = 16; o; o >>= 1) v += __shfl_xor_sync(FULL, v, o);
                if (lane == 0) scal[0] = sqrtf(v);
            }
            if (wid >= 1 && wid <= 4) {
                int r = wid - 1;
                float a0 = rkS[r*64+lane], a1 = rkS[r*64+lane+32];
                float ss = a0*a0 + a1*a1;
                #pragma unroll
                for (int o = 16; o; o >>= 1) ss += __shfl_xor_sync(FULL, ss, o);
                if (lane == 0) rknS[r] = sqrtf(ss);
            }
            if (tid >= 160 && tid < 288) {
                int n = tid - 160;
                float4 rw4 = *(const float4*)(rwoldN + n*4);
                float psi = (1.f - fgS[0]*rw4.x)*(1.f - fgS[1]*rw4.y)
                          * (1.f - fgS[2]*rw4.z)*(1.f - fgS[3]*rw4.w);
                float uo = uS[n], wo = wwPer[n];
                float un = (uo + wo - uo*wo) * psi;
                suS[n] = un;
                uS[n] = un;
            }
            __syncthreads();

            // P2: warp0 sort+scan+alloc; warps 8-11 content write scores (old mem, old norms)
            if (wid == 0) {
                float v[4];
                #pragma unroll
                for (int s = 0; s < 4; s++) v[s] = suS[s*32 + lane];
                #pragma unroll
                for (int k = 2; k <= 128; k <<= 1) {
                    for (int j = k >> 1; j >= 32; j >>= 1) {
                        int js = j >> 5;
                        #pragma unroll
                        for (int s = 0; s < 4; s++) if (!(s & js)) {
                            int sp = s | js;
                            bool up = (((s*32 + lane) & k) == 0);
                            float lo = v[s], hi = v[sp];
                            float mn = fminf(lo, hi), mx = fmaxf(lo, hi);
                            v[s]  = up ? mn : mx;
                            v[sp] = up ? mx : mn;
                        }
                    }
                    for (int j = ((k>>1) > 16 ? 16 : (k>>1)); j >= 1; j >>= 1) {
                        #pragma unroll
                        for (int s = 0; s < 4; s++) {
                            bool up = (((s*32 + lane) & k) == 0);
                            float o = __shfl_xor_sync(FULL, v[s], j);
                            bool lower = ((lane & j) == 0);
                            v[s] = (up == lower) ? fminf(v[s], o) : fmaxf(v[s], o);
                        }
                    }
                }
                #pragma unroll
                for (int s = 0; s < 4; s++) suS[s*32 + lane] = v[s];
                __syncwarp();
                float w0 = suS[lane*4+0], w1 = suS[lane*4+1], w2 = suS[lane*4+2], w3 = suS[lane*4+3];
                float pl = w0*w1*w2*w3;
                float incl = pl;
                #pragma unroll
                for (int off = 1; off < 32; off <<= 1) {
                    float tv = __shfl_up_sync(FULL, incl, off);
                    if (lane >= off) incl *= tv;
                }
                float base = __shfl_up_sync(FULL, incl, 1);
                if (lane == 0) base = 1.f;
                float run = base;
                aAl[lane*4+0] = (1.f - w0)*run; run *= w0;
                aAl[lane*4+1] = (1.f - w1)*run; run *= w1;
                aAl[lane*4+2] = (1.f - w2)*run; run *= w2;
                aAl[lane*4+3] = (1.f - w3)*run;
            } else if (wid >= 8 && wid < 12) {
                int n = tid - 256;
                const float4* m4 = (const float4*)(memS + n*64);
                const float4* k4p = (const float4*)wkS;
                float d = 0.f;
                #pragma unroll
                for (int q = 0; q < 16; q++) {
                    float4 mv = m4[q], kv = k4p[q];
                    d += mv.x*kv.x + mv.y*kv.y + mv.z*kv.z + mv.w*kv.w;
                }
                cwS[n] = d / ((normM[n] + 1e-6f) * scal[0]) * scal[1];
            }
            __syncthreads();

            // P3: warp0: cw softmax -> ww -> sum -> precedence
            if (wid == 0) {
                float c0 = cwS[lane*4+0], c1 = cwS[lane*4+1], c2 = cwS[lane*4+2], c3 = cwS[lane*4+3];
                float mx = fmaxf(fmaxf(c0,c1), fmaxf(c2,c3));
                #pragma unroll
                for (int o = 16; o; o >>= 1) mx = fmaxf(mx, __shfl_xor_sync(FULL, mx, o));
                float e0 = expf(c0-mx), e1 = expf(c1-mx), e2 = expf(c2-mx), e3 = expf(c3-mx);
                float sme = e0+e1+e2+e3;
                #pragma unroll
                for (int o = 16; o; o >>= 1) sme += __shfl_xor_sync(FULL, sme, o);
                float inv = 1.f/sme;
                float ag = scal[2], wg = scal[3];
                float ww0 = wg*(ag*aAl[lane*4+0] + (1.f-ag)*e0*inv);
                float ww1 = wg*(ag*aAl[lane*4+1] + (1.f-ag)*e1*inv);
                float ww2 = wg*(ag*aAl[lane*4+2] + (1.f-ag)*e2*inv);
                float ww3 = wg*(ag*aAl[lane*4+3] + (1.f-ag)*e3*inv);
                wwPer[lane*4+0]=ww0; wwPer[lane*4+1]=ww1; wwPer[lane*4+2]=ww2; wwPer[lane*4+3]=ww3;
                float S = ww0+ww1+ww2+ww3;
                #pragma unroll
                for (int o = 16; o; o >>= 1) S += __shfl_xor_sync(FULL, S, o);
                float oms = 1.f - S;
                pPer[lane*4+0] = oms*pPer[lane*4+0] + ww0;
                pPer[lane*4+1] = oms*pPer[lane*4+1] + ww1;
                pPer[lane*4+2] = oms*pPer[lane*4+2] + ww2;
                pPer[lane*4+3] = oms*pPer[lane*4+3] + ww3;
            }
            __syncthreads();

            // P4a: mem write + norm partials (thread = n, quarter)
            {
                int n = n4, q = r4;
                float wwn = wwPer[n];
                float4* m4 = (float4*)(memS + n*64 + q*16);
                const float4* wv4 = (const float4*)(wvS + q*16);
                const float4* er4 = (const float4*)(erS + q*16);
                float ss = 0.f;
                #pragma unroll
                for (int i = 0; i < 4; i++) {
                    float4 m = m4[i], wv = wv4[i], er = er4[i];
                    m.x += wwn*(wv.x - er.x); m.y += wwn*(wv.y - er.y);
                    m.z += wwn*(wv.z - er.z); m.w += wwn*(wv.w - er.w);
                    m4[i] = m;
                    ss += m.x*m.x + m.y*m.y + m.z*m.z + m.w*m.w;
                }
                normP[n*4 + q] = ss;
            }
            __syncthreads();

            // P4b: content-read scores (thread = n, r) + store new norms
            {
                int n = n4, r = r4;
                float ssn = normP[n*4+0] + normP[n*4+1] + normP[n*4+2] + normP[n*4+3];
                float nrm = sqrtf(ssn);
                const float4* m4 = (const float4*)(memS + n*64);
                const float4* rk4 = (const float4*)(rkS + r*64);
                float c = 0.f;
                #pragma unroll
                for (int q = 0; q < 16; q++) {
                    float4 mv = m4[q], kv = rk4[q];
                    c += mv.x*kv.x + mv.y*kv.y + mv.z*kv.z + mv.w*kv.w;
                }
                crS[n*4+r] = c / (nrm + 1e-6f) / rknS[r] * rsS[r];
                if (r == 0) normM[n] = nrm;   // old norms for next step's P2
            }
            __syncthreads();

            // P5a: links update + bwd partials (16 warps x 8 rows)
            {
                float pj[4], wwj[4], bw[4][4];
                #pragma unroll
                for (int q = 0; q < 4; q++) {
                    pj[q] = pPer[lane+32*q]; wwj[q] = wwPer[lane+32*q];
                    #pragma unroll
                    for (int r = 0; r < 4; r++) bw[q][r] = 0.f;
                }
                int i0 = wid * 8;
                for (int ii = 0; ii < 8; ii++) {
                    int i = i0 + ii;
                    float wi = wwPer[i];
                    float ri0 = rwoldN[i*4+0], ri1 = rwoldN[i*4+1], ri2 = rwoldN[i*4+2], ri3 = rwoldN[i*4+3];
                    #pragma unroll
                    for (int q = 0; q < 4; q++) {
                        int j = lane + 32*q;
                        float L = linkS[i*LNK + j];
                        L = (1.f - wi - wwj[q])*L + wi*pj[q];
                        if (i == j) L = 0.f;
                        linkS[i*LNK + j] = L;
                        bw[q][0] = fmaf(L, ri0, bw[q][0]);
                        bw[q][1] = fmaf(L, ri1, bw[q][1]);
                        bw[q][2] = fmaf(L, ri2, bw[q][2]);
                        bw[q][3] = fmaf(L, ri3, bw[q][3]);
                    }
                }
                #pragma unroll
                for (int q = 0; q < 4; q++)
                    #pragma unroll
                    for (int r = 0; r < 4; r++)
                        bwdP[wid*512 + (lane+32*q)*4 + r] = bw[q][r];
            }
            __syncthreads();

            // P5b: fwd walk (thread = n, r), new links x old rw
            {
                int n = n4, r = r4;
                const float4* L4 = (const float4*)(linkS + n*LNK);
                const float4* rw4 = (const float4*)(rwoldT + r*128);
                float f = 0.f;
                #pragma unroll
                for (int q = 0; q < 32; q++) {
                    float4 lv = L4[q], rv = rw4[q];
                    f += lv.x*rv.x + lv.y*rv.y + lv.z*rv.z + lv.w*rv.w;
                }
                fwdS[n*4+r] = f;
            }
            __syncthreads();

            // P6: cr softmax (warps 0-3) + bwd reduce (warps 4-7)
            if (wid < 4) {
                int r = wid;
                float m = -1e30f;
                #pragma unroll
                for (int q = 0; q < 4; q++) m = fmaxf(m, crS[(lane + 32*q)*4 + r]);
                #pragma unroll
                for (int o = 16; o; o >>= 1) m = fmaxf(m, __shfl_xor_sync(FULL, m, o));
                float s_ = 0.f;
                #pragma unroll
                for (int q = 0; q < 4; q++) s_ += expf(crS[(lane + 32*q)*4 + r] - m);
                #pragma unroll
                for (int o = 16; o; o >>= 1) s_ += __shfl_xor_sync(FULL, s_, o);
                if (lane == 0) { red[r*2] = m; red[r*2+1] = s_; }
            } else if (wid < 8) {
                int t2 = (wid - 4)*32 + lane;
                #pragma unroll
                for (int q = 0; q < 4; q++) {
                    int jr = t2 + 128*q;
                    float acc = 0.f;
                    #pragma unroll
                    for (int w16 = 0; w16 < 16; w16++) acc += bwdP[w16*512 + jr];
                    bwdS[jr] = acc;
                }
            }
            __syncthreads();

            // P7: new read weights
            if (tid < 128) {
                int n = tid;
                #pragma unroll
                for (int r = 0; r < 4; r++) {
                    float c = expf(crS[n*4+r] - red[r*2]) / red[r*2+1];
                    float v = rmS[r*3+0]*bwdS[n*4+r] + rmS[r*3+1]*c + rmS[r*3+2]*fwdS[n*4+r];
                    rwnewS[n*4+r] = v;
                }
            }
            __syncthreads();

            // P8: read vectors + rw rotate (both layouts)
            if (tid < 256) {
                int w = tid >> 2, r = tid & 3;
                float acc = 0.f;
                #pragma unroll 8
                for (int n = 0; n < 128; n++) acc = fmaf(memS[n*64+w], rwnewS[n*4+r], acc);
                g_r[b*256 + w*4 + r] = acc;
                out[((size_t)t*B_ + b)*HR + 512 + w*4 + r] = acc;
            }
            rwoldN[tid] = rwnewS[tid];
            rwoldT[(tid & 3)*128 + (tid >> 2)] = rwnewS[tid];
        }
        gbar(tgt);   // g_r visible for next gates
    }

    // ---- tail: copy hrs[-1] ----
    if (tid < 384) {
        int idx = bid*384 + tid;
        out[(size_t)T_*B_*HR + idx] = __ldcg(out + (size_t)(T_-1)*B_*HR + idx);
    }
}

extern "C" void kernel_launch(void* const* d_in, const int* in_sizes, int n_in,
                              void* d_out, int out_size) {
    const float* x    = (const float*)d_in[0];
    const float* M0   = (const float*)d_in[1];
    const float* W_ih = (const float*)d_in[2];
    const float* b_ih = (const float*)d_in[3];
    const float* W_hh = (const float*)d_in[4];
    const float* b_hh = (const float*)d_in[5];
    const float* Wrk  = (const float*)d_in[6];
    const float* brk  = (const float*)d_in[7];
    const float* Wrs  = (const float*)d_in[8];
    const float* brs  = (const float*)d_in[9];
    const float* Wwk  = (const float*)d_in[10];
    const float* bwk  = (const float*)d_in[11];
    const float* Wws  = (const float*)d_in[12];
    const float* bws  = (const float*)d_in[13];
    const float* We   = (const float*)d_in[14];
    const float* be   = (const float*)d_in[15];
    const float* Wv   = (const float*)d_in[16];
    const float* bv   = (const float*)d_in[17];
    const float* Wfg  = (const float*)d_in[18];
    const float* bfg  = (const float*)d_in[19];
    const float* Wag  = (const float*)d_in[20];
    const float* bag  = (const float*)d_in[21];
    const float* Wwg  = (const float*)d_in[22];
    const float* bwg  = (const float*)d_in[23];
    const float* Wrm  = (const float*)d_in[24];
    const float* brm  = (const float*)d_in[25];
    float* out = (float*)d_out;

    cudaFuncSetAttribute(k_dnc, cudaFuncAttributeMaxDynamicSharedMemorySize, SM_BYTES);

    k_init<<<128, 256>>>();
    k_dnc<<<GRID_, TPB_, SM_BYTES>>>(x, M0, W_ih, b_ih, W_hh, b_hh,
        Wrk, brk, Wrs, brs, Wwk, bwk, Wws, bws, We, be, Wv, bv,
        Wfg, bfg, Wag, bag, Wwg, bwg, Wrm, brm, out);
}

// round 12
// speedup vs baseline: 3.4530x; 1.2542x over previous
#include <cuda_runtime.h>
#include <math.h>
#include <stdint.h>
#include <stddef.h>

#define T_   128
#define B_   64
#define D_   256
#define H_   512
#define R_   4
#define N_   128
#define W_   64
#define HR   768
#define NIF  471
#define NIFP 480
#define GRID_ 128
#define TPB_  512

__device__ __align__(16) float g_h[2][B_*H_];
__device__ __align__(16) float g_r[B_*R_*W_];
__device__ __align__(16) float g_if[B_*NIFP];
__device__ unsigned g_bar;

__device__ __forceinline__ float sigm(float x) { return 1.f/(1.f+expf(-x)); }
__device__ __forceinline__ float oneplus(float v) {
    float sp = (v > 20.f) ? v : log1pf(expf(v));
    return 1.f + sp;
}
__device__ __forceinline__ void fma2(unsigned long long &d, unsigned long long a, unsigned long long b) {
    asm("fma.rn.f32x2 %0, %1, %2, %3;" : "=l"(d) : "l"(a), "l"(b), "l"(d));
}
__device__ __forceinline__ float f2sum(unsigned long long v) {
    float lo = __uint_as_float((unsigned)(v & 0xffffffffull));
    float hi = __uint_as_float((unsigned)(v >> 32));
    return lo + hi;
}
#define CP_CG(dst, src) asm volatile("cp.async.cg.shared.global [%0], [%1], 16;" :: "r"(dst), "l"(src))
#define CP_COMMIT()     asm volatile("cp.async.commit_group;")
#define CP_WAIT2()      asm volatile("cp.async.wait_group 2;")
#define CP_WAIT1()      asm volatile("cp.async.wait_group 1;")
#define CP_WAIT0()      asm volatile("cp.async.wait_group 0;")

__device__ __forceinline__ void gbar(unsigned &tgt) {
    __syncthreads();
    if (threadIdx.x == 0) {
        __threadfence();
        atomicAdd(&g_bar, 1u);
        unsigned v;
        do {
            asm volatile("ld.acquire.gpu.u32 %0, [%1];" : "=r"(v) : "l"(&g_bar) : "memory");
            if (v < tgt) __nanosleep(20);
        } while (v < tgt);
    }
    __syncthreads();
    tgt += GRID_;
}

__global__ void k_init() {
    int i = blockIdx.x*blockDim.x + threadIdx.x;
    int stride = gridDim.x*blockDim.x;
    for (int idx = i; idx < 2*B_*H_; idx += stride) ((float*)g_h)[idx] = 0.f;
    for (int idx = i; idx < B_*R_*W_; idx += stride) g_r[idx] = 0.f;
    if (i == 0) g_bar = 0u;
}

// smem layout (floats)
#define LNK 132
#define OFF_LINK 0                          // 128*132 = 16896
#define OFF_MEM  16896                      // 8192
#define OFF_RWN  (16896+8192)               // 512
#define OFF_RWT  (OFF_RWN+512)              // 512
#define OFF_U    (OFF_RWT+512)              // 128
#define OFF_P    (OFF_U+128)                // 128
#define OFF_WW   (OFF_P+128)                // 128
#define OFF_S    (OFF_WW+128)               // 256
#define OFF_NORM (OFF_S+256)                // 128
#define OFF_SCR  (OFF_NORM+128)
#define SCR_FLOATS 16640
#define SM_FLOATS (OFF_SCR + SCR_FLOATS)
#define SM_BYTES  (SM_FLOATS*4)

__global__ void __launch_bounds__(TPB_, 1) k_dnc(
    const float* __restrict__ x, const float* __restrict__ M0,
    const float* __restrict__ W_ih, const float* __restrict__ b_ih,
    const float* __restrict__ W_hh, const float* __restrict__ b_hh,
    const float* __restrict__ Wrk, const float* __restrict__ brk,
    const float* __restrict__ Wrs, const float* __restrict__ brs,
    const float* __restrict__ Wwk, const float* __restrict__ bwk,
    const float* __restrict__ Wws, const float* __restrict__ bws,
    const float* __restrict__ We,  const float* __restrict__ be,
    const float* __restrict__ Wv,  const float* __restrict__ bv,
    const float* __restrict__ Wfg, const float* __restrict__ bfg,
    const float* __restrict__ Wag, const float* __restrict__ bag,
    const float* __restrict__ Wwg, const float* __restrict__ bwg,
    const float* __restrict__ Wrm, const float* __restrict__ brm,
    float* __restrict__ out)
{
    extern __shared__ float sm[];
    float* linkS  = sm + OFF_LINK;
    float* memS   = sm + OFF_MEM;
    float* rwoldN = sm + OFF_RWN;
    float* rwoldT = sm + OFF_RWT;
    float* uS     = sm + OFF_U;
    float* pPer   = sm + OFF_P;
    float* wwPer  = sm + OFF_WW;
    float* sS     = sm + OFF_S;
    float* normM  = sm + OFF_NORM;
    float* scr    = sm + OFF_SCR;
    // state scratch (aliases gates/iface scratch)
    float* rwnewS= scr;          // 512
    float* crS   = scr + 512;    // 512
    float* fwdS  = scr + 1024;   // 512
    float* bwdS  = scr + 1536;   // 512
    float* bwdP  = scr + 2048;   // 8192
    float* suS   = scr + 10240;  // 128
    float* aAl   = scr + 10368;  // 128
    float* cwS   = scr + 10496;  // 128
    float* normP = scr + 10624;  // 512
    float* rkS   = scr + 11136;  // 256
    float* wkS   = scr + 11392;  // 64
    float* erS   = scr + 11456;  // 64
    float* wvS   = scr + 11520;  // 64
    float* fgS   = scr + 11584;  // 4
    float* rsS   = scr + 11588;  // 4
    float* rmS   = scr + 11592;  // 12
    float* rknS  = scr + 11604;  // 4
    float* scal  = scr + 11608;  // 8
    float* red   = scr + 11616;  // 8
    float* gpart = scr;          // gates partials [16rows][64b][16ks] = 16384 (aliases buffers)

    const int tid  = threadIdx.x;
    const int lane = tid & 31, wid = tid >> 5;
    const int bid  = blockIdx.x;
    const unsigned FULL = 0xffffffffu;
    unsigned tgt = GRID_;

    uint32_t smemU32;
    asm("{ .reg .u64 t0; cvta.to.shared.u64 t0, %1; cvt.u32.u64 %0, t0; }" : "=r"(smemU32) : "l"(sm));

    // ---- one-time smem init ----
    if (bid < 64) {
        for (int i = tid; i < N_*W_; i += TPB_) memS[i] = M0[i];
        for (int i = tid; i < N_*LNK; i += TPB_) linkS[i] = 0.f;
        if (tid < 512) { rwoldN[tid] = 0.f; rwoldT[tid] = 0.f; }
        if (tid < 128) { uS[tid] = 1e-6f; pPer[tid] = 0.f; wwPer[tid] = 0.f; }
    }
    if (tid < 256) sS[tid] = 0.f;
    __syncthreads();
    if (bid < 64 && tid < 128) {
        float ss = 0.f;
        for (int k = 0; k < 64; k++) { float v = memS[tid*64+k]; ss += v*v; }
        normM[tid] = sqrtf(ss);
    }
    __syncthreads();

    const int jbase = bid * 4;
    // gates decomposition: jg(2) x bg(16) x ks(16)
    const int jg = tid >> 8;
    const int bg = (tid >> 4) & 15;
    const int ks = tid & 15;

    for (int t = 0; t < T_; t++) {
        // ================= gates phase (all 128 blocks) =================
        {
            const float* hprev = g_h[t & 1];
            float* aBs[3] = {scr, scr + 4352, scr + 8704};
            float* wBs[3] = {scr + 13056, scr + 14080, scr + 15104};

            auto gstage = [&](int cc) {
                int pb = cc % 3;
                int k0 = cc * 64;
                const float* src; size_t strd;
                if (k0 < 256)      { src = x + (size_t)t*B_*D_ + k0; strd = D_; }
                else if (k0 < 512) { src = g_r + (k0-256);           strd = 256; }
                else               { src = hprev + (k0-512);         strd = H_; }
                uint32_t aDst = smemU32 + (uint32_t)(OFF_SCR + pb*4352)*4u;
                int f0 = tid, f1 = tid + 512;
                CP_CG(aDst + (uint32_t)((f0>>4)*68 + (f0&15)*4)*4u, src + (size_t)(f0>>4)*strd + (f0&15)*4);
                CP_CG(aDst + (uint32_t)((f1>>4)*68 + (f1&15)*4)*4u, src + (size_t)(f1>>4)*strd + (f1&15)*4);
                if (tid < 256) {
                    int row = tid >> 4, k4 = tid & 15;
                    int c2 = row >> 2, g = row & 3;
                    int G = g*H_ + jbase + c2;
                    const float* wp = (k0 < 512) ? (W_ih + (size_t)G*512 + k0)
                                                 : (W_hh + (size_t)G*512 + (k0-512));
                    uint32_t wDst = smemU32 + (uint32_t)(OFF_SCR + 13056 + pb*1024 + row*64 + k4*4)*4u;
                    CP_CG(wDst, wp + k4*4);
                }
                CP_COMMIT();
            };

            gstage(0); gstage(1);
            unsigned long long acc[32];
            #pragma unroll
            for (int i = 0; i < 32; i++) acc[i] = 0ull;

            for (int c = 0; c < 16; c++) {
                if (c + 2 < 16) { gstage(c + 2); CP_WAIT2(); }
                else if (c + 1 < 16) { CP_WAIT1(); }
                else { CP_WAIT0(); }
                __syncthreads();
                int pb = c % 3;
                const float* aB = aBs[pb];
                const float* wB = wBs[pb];
                ulonglong2 A2[4];
                #pragma unroll
                for (int bi = 0; bi < 4; bi++)
                    A2[bi] = *(const ulonglong2*)(aB + (bg*4+bi)*68 + ks*4);
                #pragma unroll
                for (int r8 = 0; r8 < 8; r8++) {
                    ulonglong2 W2 = *(const ulonglong2*)(wB + (jg*8+r8)*64 + ks*4);
                    fma2(acc[0*8+r8], A2[0].x, W2.x); fma2(acc[0*8+r8], A2[0].y, W2.y);
                    fma2(acc[1*8+r8], A2[1].x, W2.x); fma2(acc[1*8+r8], A2[1].y, W2.y);
                    fma2(acc[2*8+r8], A2[2].x, W2.x); fma2(acc[2*8+r8], A2[2].y, W2.y);
                    fma2(acc[3*8+r8], A2[3].x, W2.x); fma2(acc[3*8+r8], A2[3].y, W2.y);
                }
            }
            __syncthreads();   // buffers free -> gpart alias safe
            #pragma unroll
            for (int bi = 0; bi < 4; bi++)
                #pragma unroll
                for (int r8 = 0; r8 < 8; r8++)
                    gpart[((jg*8+r8)*64 + bg*4+bi)*16 + ks] = f2sum(acc[bi*8+r8]);
            __syncthreads();
            float red0 = 0.f, red1 = 0.f;
            {
                const float* p0 = gpart + tid*16;
                const float* p1 = gpart + (tid+512)*16;
                #pragma unroll
                for (int q = 0; q < 16; q++) { red0 += p0[q]; red1 += p1[q]; }
            }
            __syncthreads();
            gpart[tid] = red0; gpart[tid+512] = red1;
            __syncthreads();
            if (tid < 256) {
                int c2 = tid >> 6, b3 = tid & 63;
                int j = jbase + c2;
                float gv[4];
                #pragma unroll
                for (int g = 0; g < 4; g++)
                    gv[g] = gpart[(c2*4+g)*64 + b3] + b_ih[g*H_+j] + b_hh[g*H_+j];
                float sold = sS[c2*64 + b3];
                float snew = sigm(gv[1])*sold + sigm(gv[0])*tanhf(gv[2]);
                float hnew = sigm(gv[3])*tanhf(snew);
                sS[c2*64 + b3] = snew;
                g_h[(t&1)^1][b3*H_ + j] = hnew;
                out[((size_t)t*B_ + b3)*HR + j] = hnew;
            }
        }
        gbar(tgt);   // barA: h visible

        // ================= iface phase (blocks 0..117, 4 cols each) =================
        if (bid < 118) {
            const float* hcur = g_h[(t&1)^1];
            int Cbase = bid * 4;
            float* hBs[2] = {scr, scr + 4352};
            float* biasS  = scr + 9216;
            float* gpartI = scr + 9232;        // [256 out][16 ks]
            const int ibg = tid >> 4;          // 0..31 (2 batches)
            const int iks = tid & 15;

            auto istage = [&](int c) {
                int pb = c & 1;
                int k0 = c * 64;
                uint32_t aDst = smemU32 + (uint32_t)(OFF_SCR + pb*4352)*4u;
                int f0 = tid, f1 = tid + 512;
                CP_CG(aDst + (uint32_t)((f0>>4)*68 + (f0&15)*4)*4u, hcur + (size_t)(f0>>4)*H_ + k0 + (f0&15)*4);
                CP_CG(aDst + (uint32_t)((f1>>4)*68 + (f1&15)*4)*4u, hcur + (size_t)(f1>>4)*H_ + k0 + (f1&15)*4);
                if (tid < 64) {
                    int row = tid >> 4, k4 = tid & 15;
                    int C = Cbase + row;
                    const float* wp = Wws;     // dummy-valid for C >= NIF
                    if (C < 256)       { int w = C>>2, r = C&3; wp = Wrk + ((size_t)r*W_ + w)*H_; }
                    else if (C < 260)  wp = Wrs + (C-256)*H_;
                    else if (C < 272)  wp = Wrm + (C-260)*H_;
                    else if (C < 276)  wp = Wfg + (C-272)*H_;
                    else if (C < 340)  wp = Wwk + (C-276)*H_;
                    else if (C == 340) wp = Wws;
                    else if (C < 405)  wp = We + (C-341)*H_;
                    else if (C < 469)  wp = Wv + (C-405)*H_;
                    else if (C == 469) wp = Wag;
                    else if (C == 470) wp = Wwg;
                    uint32_t wDst = smemU32 + (uint32_t)(OFF_SCR + 8704 + pb*256 + row*64 + k4*4)*4u;
                    CP_CG(wDst, wp + k0 + k4*4);
                }
                CP_COMMIT();
            };

            if (tid < 4) {
                int C = Cbase + tid; float bb = 0.f;
                if (C < 256)       { int w = C>>2, r = C&3; bb = brk[r*W_ + w]; }
                else if (C < 260)  bb = brs[C-256];
                else if (C < 272)  bb = brm[C-260];
                else if (C < 276)  bb = bfg[C-272];
                else if (C < 340)  bb = bwk[C-276];
                else if (C == 340) bb = bws[0];
                else if (C < 405)  bb = be[C-341];
                else if (C < 469)  bb = bv[C-405];
                else if (C == 469) bb = bag[0];
                else if (C == 470) bb = bwg[0];
                biasS[tid] = bb;
            }
            istage(0);
            unsigned long long acc[8];
            #pragma unroll
            for (int i = 0; i < 8; i++) acc[i] = 0ull;

            for (int c = 0; c < 8; c++) {
                if (c + 1 < 8) { istage(c + 1); CP_WAIT1(); }
                else { CP_WAIT0(); }
                __syncthreads();
                int pb = c & 1;
                const float* hB = hBs[pb];
                const float* wI = scr + 8704 + pb*256;
                ulonglong2 A0 = *(const ulonglong2*)(hB + (ibg*2+0)*68 + iks*4);
                ulonglong2 A1 = *(const ulonglong2*)(hB + (ibg*2+1)*68 + iks*4);
                #pragma unroll
                for (int cc = 0; cc < 4; cc++) {
                    ulonglong2 W2 = *(const ulonglong2*)(wI + cc*64 + iks*4);
                    fma2(acc[0*4+cc], A0.x, W2.x); fma2(acc[0*4+cc], A0.y, W2.y);
                    fma2(acc[1*4+cc], A1.x, W2.x); fma2(acc[1*4+cc], A1.y, W2.y);
                }
            }
            __syncthreads();
            #pragma unroll
            for (int bi = 0; bi < 2; bi++)
                #pragma unroll
                for (int cc = 0; cc < 4; cc++)
                    gpartI[(cc*64 + ibg*2+bi)*16 + iks] = f2sum(acc[bi*4+cc]);
            __syncthreads();
            if (tid < 256) {
                int cc = tid >> 6, b3 = tid & 63;
                int C = Cbase + cc;
                if (C < NIF) {
                    const float* p = gpartI + tid*16;
                    float s_ = 0.f;
                    #pragma unroll
                    for (int q = 0; q < 16; q++) s_ += p[q];
                    g_if[b3*NIFP + C] = s_ + biasS[cc];
                }
            }
        }
        gbar(tgt);   // barB: g_if visible

        // ================= state phase (blocks 0..63) =================
        if (bid < 64) {
            const int b = bid;
            const float* ifr = g_if + b*NIFP;
            const int n4 = tid >> 2, r4 = tid & 3;

            if (tid < 256) { int w = tid >> 2, r = tid & 3; rkS[r*64 + w] = __ldcg(ifr + tid); }
            else if (tid < 320) { int i = tid-256; wkS[i] = __ldcg(ifr + 276 + i); }
            else if (tid < 384) { int i = tid-320; erS[i] = sigm(__ldcg(ifr + 341 + i)); }
            else if (tid < 448) { int i = tid-384; wvS[i] = sigm(__ldcg(ifr + 405 + i)); }
            else if (tid < 452) {
                int i = tid-448;
                fgS[i] = sigm(__ldcg(ifr + 272 + i));
                rsS[i] = oneplus(__ldcg(ifr + 256 + i));
                float m0 = __ldcg(ifr+260+i*3+0), m1 = __ldcg(ifr+260+i*3+1), m2 = __ldcg(ifr+260+i*3+2);
                float mx = fmaxf(m0, fmaxf(m1, m2));
                float e0 = expf(m0-mx), e1 = expf(m1-mx), e2 = expf(m2-mx);
                float si = e0+e1+e2;
                rmS[i*3+0]=e0/si; rmS[i*3+1]=e1/si; rmS[i*3+2]=e2/si;
            }
            else if (tid == 500) {
                scal[1] = oneplus(__ldcg(ifr + 340));
                scal[2] = sigm(__ldcg(ifr + 469));
                scal[3] = sigm(__ldcg(ifr + 470));
            }
            __syncthreads();

            if (wid == 0) {
                float v = wkS[lane]*wkS[lane] + wkS[lane+32]*wkS[lane+32];
                #pragma unroll
                for (int o = 16; o; o >>= 1) v += __shfl_xor_sync(FULL, v, o);
                if (lane == 0) scal[0] = sqrtf(v);
            }
            if (wid >= 1 && wid <= 4) {
                int r = wid - 1;
                float a0 = rkS[r*64+lane], a1 = rkS[r*64+lane+32];
                float ss = a0*a0 + a1*a1;
                #pragma unroll
                for (int o = 16; o; o >>= 1) ss += __shfl_xor_sync(FULL, ss, o);
                if (lane == 0) rknS[r] = sqrtf(ss);
            }
            if (tid >= 160 && tid < 288) {
                int n = tid - 160;
                float4 rw4 = *(const float4*)(rwoldN + n*4);
                float psi = (1.f - fgS[0]*rw4.x)*(1.f - fgS[1]*rw4.y)
                          * (1.f - fgS[2]*rw4.z)*(1.f - fgS[3]*rw4.w);
                float uo = uS[n], wo = wwPer[n];
                float un = (uo + wo - uo*wo) * psi;
                suS[n] = un;
                uS[n] = un;
            }
            __syncthreads();

            if (wid == 0) {
                float v[4];
                #pragma unroll
                for (int s = 0; s < 4; s++) v[s] = suS[s*32 + lane];
                #pragma unroll
                for (int k = 2; k <= 128; k <<= 1) {
                    for (int j = k >> 1; j >= 32; j >>= 1) {
                        int js = j >> 5;
                        #pragma unroll
                        for (int s = 0; s < 4; s++) if (!(s & js)) {
                            int sp = s | js;
                            bool up = (((s*32 + lane) & k) == 0);
                            float lo = v[s], hi = v[sp];
                            float mn = fminf(lo, hi), mx = fmaxf(lo, hi);
                            v[s]  = up ? mn : mx;
                            v[sp] = up ? mx : mn;
                        }
                    }
                    for (int j = ((k>>1) > 16 ? 16 : (k>>1)); j >= 1; j >>= 1) {
                        #pragma unroll
                        for (int s = 0; s < 4; s++) {
                            bool up = (((s*32 + lane) & k) == 0);
                            float o = __shfl_xor_sync(FULL, v[s], j);
                            bool lower = ((lane & j) == 0);
                            v[s] = (up == lower) ? fminf(v[s], o) : fmaxf(v[s], o);
                        }
                    }
                }
                #pragma unroll
                for (int s = 0; s < 4; s++) suS[s*32 + lane] = v[s];
                __syncwarp();
                float w0 = suS[lane*4+0], w1 = suS[lane*4+1], w2 = suS[lane*4+2], w3 = suS[lane*4+3];
                float pl = w0*w1*w2*w3;
                float incl = pl;
                #pragma unroll
                for (int off = 1; off < 32; off <<= 1) {
                    float tv = __shfl_up_sync(FULL, incl, off);
                    if (lane >= off) incl *= tv;
                }
                float base = __shfl_up_sync(FULL, incl, 1);
                if (lane == 0) base = 1.f;
                float run = base;
                aAl[lane*4+0] = (1.f - w0)*run; run *= w0;
                aAl[lane*4+1] = (1.f - w1)*run; run *= w1;
                aAl[lane*4+2] = (1.f - w2)*run; run *= w2;
                aAl[lane*4+3] = (1.f - w3)*run;
            } else if (wid >= 8 && wid < 12) {
                int n = tid - 256;
                const float4* m4 = (const float4*)(memS + n*64);
                const float4* k4p = (const float4*)wkS;
                float d = 0.f;
                #pragma unroll
                for (int q = 0; q < 16; q++) {
                    float4 mv = m4[q], kv = k4p[q];
                    d += mv.x*kv.x + mv.y*kv.y + mv.z*kv.z + mv.w*kv.w;
                }
                cwS[n] = d / ((normM[n] + 1e-6f) * scal[0]) * scal[1];
            }
            __syncthreads();

            if (wid == 0) {
                float c0 = cwS[lane*4+0], c1 = cwS[lane*4+1], c2 = cwS[lane*4+2], c3 = cwS[lane*4+3];
                float mx = fmaxf(fmaxf(c0,c1), fmaxf(c2,c3));
                #pragma unroll
                for (int o = 16; o; o >>= 1) mx = fmaxf(mx, __shfl_xor_sync(FULL, mx, o));
                float e0 = expf(c0-mx), e1 = expf(c1-mx), e2 = expf(c2-mx), e3 = expf(c3-mx);
                float sme = e0+e1+e2+e3;
                #pragma unroll
                for (int o = 16; o; o >>= 1) sme += __shfl_xor_sync(FULL, sme, o);
                float inv = 1.f/sme;
                float ag = scal[2], wg = scal[3];
                float ww0 = wg*(ag*aAl[lane*4+0] + (1.f-ag)*e0*inv);
                float ww1 = wg*(ag*aAl[lane*4+1] + (1.f-ag)*e1*inv);
                float ww2 = wg*(ag*aAl[lane*4+2] + (1.f-ag)*e2*inv);
                float ww3 = wg*(ag*aAl[lane*4+3] + (1.f-ag)*e3*inv);
                wwPer[lane*4+0]=ww0; wwPer[lane*4+1]=ww1; wwPer[lane*4+2]=ww2; wwPer[lane*4+3]=ww3;
                float S = ww0+ww1+ww2+ww3;
                #pragma unroll
                for (int o = 16; o; o >>= 1) S += __shfl_xor_sync(FULL, S, o);
                float oms = 1.f - S;
                pPer[lane*4+0] = oms*pPer[lane*4+0] + ww0;
                pPer[lane*4+1] = oms*pPer[lane*4+1] + ww1;
                pPer[lane*4+2] = oms*pPer[lane*4+2] + ww2;
                pPer[lane*4+3] = oms*pPer[lane*4+3] + ww3;
            }
            __syncthreads();

            {
                int n = n4, q = r4;
                float wwn = wwPer[n];
                float4* m4 = (float4*)(memS + n*64 + q*16);
                const float4* wv4 = (const float4*)(wvS + q*16);
                const float4* er4 = (const float4*)(erS + q*16);
                float ss = 0.f;
                #pragma unroll
                for (int i = 0; i < 4; i++) {
                    float4 m = m4[i], wv = wv4[i], er = er4[i];
                    m.x += wwn*(wv.x - er.x); m.y += wwn*(wv.y - er.y);
                    m.z += wwn*(wv.z - er.z); m.w += wwn*(wv.w - er.w);
                    m4[i] = m;
                    ss += m.x*m.x + m.y*m.y + m.z*m.z + m.w*m.w;
                }
                normP[n*4 + q] = ss;
            }
            __syncthreads();

            {
                int n = n4, r = r4;
                float ssn = normP[n*4+0] + normP[n*4+1] + normP[n*4+2] + normP[n*4+3];
                float nrm = sqrtf(ssn);
                const float4* m4 = (const float4*)(memS + n*64);
                const float4* rk4 = (const float4*)(rkS + r*64);
                float c = 0.f;
                #pragma unroll
                for (int q = 0; q < 16; q++) {
                    float4 mv = m4[q], kv = rk4[q];
                    c += mv.x*kv.x + mv.y*kv.y + mv.z*kv.z + mv.w*kv.w;
                }
                crS[n*4+r] = c / (nrm + 1e-6f) / rknS[r] * rsS[r];
                if (r == 0) normM[n] = nrm;
            }
            __syncthreads();

            {
                float pj[4], wwj[4], bw[4][4];
                #pragma unroll
                for (int q = 0; q < 4; q++) {
                    pj[q] = pPer[lane+32*q]; wwj[q] = wwPer[lane+32*q];
                    #pragma unroll
                    for (int r = 0; r < 4; r++) bw[q][r] = 0.f;
                }
                int i0 = wid * 8;
                for (int ii = 0; ii < 8; ii++) {
                    int i = i0 + ii;
                    float wi = wwPer[i];
                    float ri0 = rwoldN[i*4+0], ri1 = rwoldN[i*4+1], ri2 = rwoldN[i*4+2], ri3 = rwoldN[i*4+3];
                    #pragma unroll
                    for (int q = 0; q < 4; q++) {
                        int j = lane + 32*q;
                        float L = linkS[i*LNK + j];
                        L = (1.f - wi - wwj[q])*L + wi*pj[q];
                        if (i == j) L = 0.f;
                        linkS[i*LNK + j] = L;
                        bw[q][0] = fmaf(L, ri0, bw[q][0]);
                        bw[q][1] = fmaf(L, ri1, bw[q][1]);
                        bw[q][2] = fmaf(L, ri2, bw[q][2]);
                        bw[q][3] = fmaf(L, ri3, bw[q][3]);
                    }
                }
                #pragma unroll
                for (int q = 0; q < 4; q++)
                    #pragma unroll
                    for (int r = 0; r < 4; r++)
                        bwdP[wid*512 + (lane+32*q)*4 + r] = bw[q][r];
            }
            __syncthreads();

            {
                int n = n4, r = r4;
                const float4* L4 = (const float4*)(linkS + n*LNK);
                const float4* rw4 = (const float4*)(rwoldT + r*128);
                float f = 0.f;
                #pragma unroll
                for (int q = 0; q < 32; q++) {
                    float4 lv = L4[q], rv = rw4[q];
                    f += lv.x*rv.x + lv.y*rv.y + lv.z*rv.z + lv.w*rv.w;
                }
                fwdS[n*4+r] = f;
            }
            __syncthreads();

            if (wid < 4) {
                int r = wid;
                float m = -1e30f;
                #pragma unroll
                for (int q = 0; q < 4; q++) m = fmaxf(m, crS[(lane + 32*q)*4 + r]);
                #pragma unroll
                for (int o = 16; o; o >>= 1) m = fmaxf(m, __shfl_xor_sync(FULL, m, o));
                float s_ = 0.f;
                #pragma unroll
                for (int q = 0; q < 4; q++) s_ += expf(crS[(lane + 32*q)*4 + r] - m);
                #pragma unroll
                for (int o = 16; o; o >>= 1) s_ += __shfl_xor_sync(FULL, s_, o);
                if (lane == 0) { red[r*2] = m; red[r*2+1] = s_; }
            } else if (wid < 8) {
                int t2 = (wid - 4)*32 + lane;
                #pragma unroll
                for (int q = 0; q < 4; q++) {
                    int jr = t2 + 128*q;
                    float acc2 = 0.f;
                    #pragma unroll
                    for (int w16 = 0; w16 < 16; w16++) acc2 += bwdP[w16*512 + jr];
                    bwdS[jr] = acc2;
                }
            }
            __syncthreads();

            if (tid < 128) {
                int n = tid;
                #pragma unroll
                for (int r = 0; r < 4; r++) {
                    float c = expf(crS[n*4+r] - red[r*2]) / red[r*2+1];
                    float v = rmS[r*3+0]*bwdS[n*4+r] + rmS[r*3+1]*c + rmS[r*3+2]*fwdS[n*4+r];
                    rwnewS[n*4+r] = v;
                }
            }
            __syncthreads();

            if (tid < 256) {
                int w = tid >> 2, r = tid & 3;
                float acc2 = 0.f;
                #pragma unroll 8
                for (int n = 0; n < 128; n++) acc2 = fmaf(memS[n*64+w], rwnewS[n*4+r], acc2);
                g_r[b*256 + w*4 + r] = acc2;
                out[((size_t)t*B_ + b)*HR + 512 + w*4 + r] = acc2;
            }
            rwoldN[tid] = rwnewS[tid];
            rwoldT[(tid & 3)*128 + (tid >> 2)] = rwnewS[tid];
        }
        gbar(tgt);   // barC: g_r visible for next gates
    }

    if (tid < 384) {
        int idx = bid*384 + tid;
        out[(size_t)T_*B_*HR + idx] = __ldcg(out + (size_t)(T_-1)*B_*HR + idx);
    }
}

extern "C" void kernel_launch(void* const* d_in, const int* in_sizes, int n_in,
                              void* d_out, int out_size) {
    const float* x    = (const float*)d_in[0];
    const float* M0   = (const float*)d_in[1];
    const float* W_ih = (const float*)d_in[2];
    const float* b_ih = (const float*)d_in[3];
    const float* W_hh = (const float*)d_in[4];
    const float* b_hh = (const float*)d_in[5];
    const float* Wrk  = (const float*)d_in[6];
    const float* brk  = (const float*)d_in[7];
    const float* Wrs  = (const float*)d_in[8];
    const float* brs  = (const float*)d_in[9];
    const float* Wwk  = (const float*)d_in[10];
    const float* bwk  = (const float*)d_in[11];
    const float* Wws  = (const float*)d_in[12];
    const float* bws  = (const float*)d_in[13];
    const float* We   = (const float*)d_in[14];
    const float* be   = (const float*)d_in[15];
    const float* Wv   = (const float*)d_in[16];
    const float* bv   = (const float*)d_in[17];
    const float* Wfg  = (const float*)d_in[18];
    const float* bfg  = (const float*)d_in[19];
    const float* Wag  = (const float*)d_in[20];
    const float* bag  = (const float*)d_in[21];
    const float* Wwg  = (const float*)d_in[22];
    const float* bwg  = (const float*)d_in[23];
    const float* Wrm  = (const float*)d_in[24];
    const float* brm  = (const float*)d_in[25];
    float* out = (float*)d_out;

    cudaFuncSetAttribute(k_dnc, cudaFuncAttributeMaxDynamicSharedMemorySize, SM_BYTES);

    k_init<<<128, 256>>>();
    k_dnc<<<GRID_, TPB_, SM_BYTES>>>(x, M0, W_ih, b_ih, W_hh, b_hh,
        Wrk, brk, Wrs, brs, Wwk, bwk, Wws, bws, We, be, Wv, bv,
        Wfg, bfg, Wag, bag, Wwg, bwg, Wrm, brm, out);
}